// round 1
// baseline (speedup 1.0000x reference)
#include <cuda_runtime.h>
#include <math.h>

// Problem constants (fixed shapes)
#define BATCH 8192
#define HID   1024
#define FOURH 4096
#define NLAYERS 4

// Scratch (no allocations allowed) ------------------------------------------
__device__ float g_z[(size_t)BATCH * FOURH];      // pre-activation z  [B, 4H] (128 MB)
__device__ float g_wsum[(size_t)HID * FOURH];     // Wx[l]+Wh[l]       [H, 4H] (16 MB)

// ---------------------------------------------------------------------------
// SGEMM: C[M,N] = A[M,K] @ B[K,N] + bias[N] (+ rowvec[m]*colvec[n] if given)
// BM=128, BN=128, BK=16, 256 threads, 8x8 microtile per thread.
// M,N,K are multiples of the tile sizes (8192, 4096, 1024) -> no bounds checks.
// ---------------------------------------------------------------------------
#define BM 128
#define BN 128
#define BK 16
#define TM 8
#define TN 8

__global__ __launch_bounds__(256) void sgemm_lstm(
    const float* __restrict__ A,     // [M,K], lda=K
    const float* __restrict__ Bm,    // [K,N], ldb=N
    float* __restrict__ C,           // [M,N]
    const float* __restrict__ rowvec, // [M] or nullptr
    const float* __restrict__ colvec, // [N] or nullptr (paired with rowvec)
    const float* __restrict__ bias,   // [N]
    int M, int N, int K)
{
    __shared__ float As[BK][BM];
    __shared__ float Bs[BK][BN];

    const int tid = threadIdx.x;
    const int tx  = tid & 15;         // 0..15  -> n microtile
    const int ty  = tid >> 4;         // 0..15  -> m microtile
    const int bm  = blockIdx.y * BM;
    const int bn  = blockIdx.x * BN;

    float acc[TM][TN];
    #pragma unroll
    for (int i = 0; i < TM; i++)
        #pragma unroll
        for (int j = 0; j < TN; j++) acc[i][j] = 0.f;

    // A-tile load mapping: 128 rows x 4 float4; thread -> (row = tid/4, c4 = tid%4), twice
    const int a_r  = tid >> 2;
    const int a_c  = (tid & 3) * 4;
    // B-tile load mapping: 16 rows x 32 float4; thread -> (row = tid/32, c4 = tid%32), twice
    const int b_r  = tid >> 5;
    const int b_c  = (tid & 31) * 4;

    for (int k0 = 0; k0 < K; k0 += BK) {
        #pragma unroll
        for (int p = 0; p < 2; p++) {
            int r = a_r + p * 64;
            float4 v = *(const float4*)(A + (size_t)(bm + r) * K + k0 + a_c);
            As[a_c + 0][r] = v.x;
            As[a_c + 1][r] = v.y;
            As[a_c + 2][r] = v.z;
            As[a_c + 3][r] = v.w;
        }
        #pragma unroll
        for (int p = 0; p < 2; p++) {
            int r = b_r + p * 8;
            *(float4*)&Bs[r][b_c] =
                *(const float4*)(Bm + (size_t)(k0 + r) * N + bn + b_c);
        }
        __syncthreads();

        #pragma unroll
        for (int kk = 0; kk < BK; kk++) {
            float a[TM], b[TN];
            *(float4*)&a[0] = *(const float4*)&As[kk][ty * TM + 0];
            *(float4*)&a[4] = *(const float4*)&As[kk][ty * TM + 4];
            *(float4*)&b[0] = *(const float4*)&Bs[kk][tx * TN + 0];
            *(float4*)&b[4] = *(const float4*)&Bs[kk][tx * TN + 4];
            #pragma unroll
            for (int i = 0; i < TM; i++)
                #pragma unroll
                for (int j = 0; j < TN; j++)
                    acc[i][j] = fmaf(a[i], b[j], acc[i][j]);
        }
        __syncthreads();
    }

    // Epilogue: + bias[n] (+ rowvec[m]*colvec[n])
    #pragma unroll
    for (int i = 0; i < TM; i++) {
        const int m = bm + ty * TM + i;
        const float rv = rowvec ? rowvec[m] : 0.f;
        #pragma unroll
        for (int j = 0; j < TN; j++) {
            const int n = bn + tx * TN + j;
            float v = acc[i][j] + bias[n];
            if (colvec) v = fmaf(rv, colvec[n], v);
            C[(size_t)m * N + n] = v;
        }
    }
}

// ---------------------------------------------------------------------------
// Elementwise: Wsum = Wx + Wh   (n multiple of 4)
// ---------------------------------------------------------------------------
__global__ void add_weights(const float* __restrict__ a,
                            const float* __restrict__ b,
                            float* __restrict__ out, int n4)
{
    int i = blockIdx.x * blockDim.x + threadIdx.x;
    if (i < n4) {
        float4 x = ((const float4*)a)[i];
        float4 y = ((const float4*)b)[i];
        float4 r;
        r.x = x.x + y.x; r.y = x.y + y.y; r.z = x.z + y.z; r.w = x.w + y.w;
        ((float4*)out)[i] = r;
    }
}

// ---------------------------------------------------------------------------
// LSTM gates: z[b, 0:H]=i, [H:2H]=f, [2H:3H]=g, [3H:4H]=o
// c_new = sigmoid(f)*c_prev + sigmoid(i)*tanh(g);  h = sigmoid(o)*tanh(c_new)
// In-place safe (c_out may alias c_prev).
// ---------------------------------------------------------------------------
__global__ void lstm_gates(const float* __restrict__ z,
                           const float* __restrict__ c_prev,
                           float* __restrict__ c_out,
                           float* __restrict__ h_out, int BH)
{
    int idx = blockIdx.x * blockDim.x + threadIdx.x;
    if (idx >= BH) return;
    int b = idx >> 10;           // / HID
    int j = idx & (HID - 1);
    const float* zr = z + (size_t)b * FOURH;
    float zi = zr[j];
    float zf = zr[HID + j];
    float zg = zr[2 * HID + j];
    float zo = zr[3 * HID + j];
    float ig = 1.f / (1.f + expf(-zi));
    float fg = 1.f / (1.f + expf(-zf));
    float gg = tanhf(zg);
    float og = 1.f / (1.f + expf(-zo));
    float c = fmaf(fg, c_prev[idx], ig * gg);
    c_out[idx] = c;
    h_out[idx] = og * tanhf(c);
}

// ---------------------------------------------------------------------------
// Head: pred[b] = dot(h[b,:], Wd) + bd   (one warp per row)
// ---------------------------------------------------------------------------
__global__ void head_kernel(const float* __restrict__ h,
                            const float* __restrict__ Wd,
                            const float* __restrict__ bd,
                            float* __restrict__ pred, int B)
{
    int warps_per_blk = blockDim.x >> 5;
    int row = blockIdx.x * warps_per_blk + (threadIdx.x >> 5);
    int lane = threadIdx.x & 31;
    if (row >= B) return;
    const float* hr = h + (size_t)row * HID;
    float s = 0.f;
    #pragma unroll 8
    for (int k = lane; k < HID; k += 32) s = fmaf(hr[k], Wd[k], s);
    #pragma unroll
    for (int off = 16; off; off >>= 1) s += __shfl_down_sync(0xffffffffu, s, off);
    if (lane == 0) pred[row] = s + bd[0];
}

// ---------------------------------------------------------------------------
extern "C" void kernel_launch(void* const* d_in, const int* in_sizes, int n_in,
                              void* d_out, int out_size)
{
    const float* x_todec = (const float*)d_in[0];  // [B,1]
    const float* c0      = (const float*)d_in[1];  // [B,H]
    const float* h0      = (const float*)d_in[2];  // [B,H]
    const float* Wx0     = (const float*)d_in[3];  // [1,4H]
    const float* Wh0     = (const float*)d_in[4];  // [H,4H]
    const float* b0      = (const float*)d_in[5];  // [4H]
    const float* Wx      = (const float*)d_in[6];  // [L-1,H,4H]
    const float* Wh      = (const float*)d_in[7];  // [L-1,H,4H]
    const float* bl      = (const float*)d_in[8];  // [L-1,4H]
    const float* Wd      = (const float*)d_in[9];  // [H,1]
    const float* bd      = (const float*)d_in[10]; // [1]
    // d_in[11] = training (ignored, deterministic 0)

    float* out  = (float*)d_out;
    float* cbuf = out;                              // [B,H]  -> final c
    float* hbuf = out + (size_t)BATCH * HID;        // [B,H]  -> final h
    float* pred = out + 2 * (size_t)BATCH * HID;    // [B]    -> x_pred

    float* z    = nullptr;
    float* wsum = nullptr;
    cudaGetSymbolAddress((void**)&z, g_z);
    cudaGetSymbolAddress((void**)&wsum, g_wsum);

    dim3 ggrid(FOURH / BN, BATCH / BM);   // (32, 64)
    dim3 gblk(256);
    const int BH = BATCH * HID;
    const int gates_blocks = (BH + 255) / 256;
    const int wn4 = HID * FOURH / 4;
    const int wadd_blocks = (wn4 + 255) / 256;

    // ---- layer 0: z = h0 @ Wh0 + x*Wx0 + b0 ----
    sgemm_lstm<<<ggrid, gblk>>>(h0, Wh0, z, x_todec, Wx0, b0,
                                BATCH, FOURH, HID);
    lstm_gates<<<gates_blocks, 256>>>(z, c0, cbuf, hbuf, BH);

    // ---- layers 1..3: x_t == h, so z = h @ (Wx[l]+Wh[l]) + b[l] ----
    for (int l = 0; l < NLAYERS - 1; l++) {
        const size_t woff = (size_t)l * HID * FOURH;
        add_weights<<<wadd_blocks, 256>>>(Wx + woff, Wh + woff, wsum, wn4);
        sgemm_lstm<<<ggrid, gblk>>>(hbuf, wsum, z, nullptr, nullptr,
                                    bl + (size_t)l * FOURH,
                                    BATCH, FOURH, HID);
        lstm_gates<<<gates_blocks, 256>>>(z, cbuf, cbuf, hbuf, BH);
    }

    // ---- head: pred = h @ Wd + bd ----
    head_kernel<<<BATCH / 8, 256>>>(hbuf, Wd, bd, pred, BATCH);
}

// round 3
// speedup vs baseline: 1.5317x; 1.5317x over previous
#include <cuda_runtime.h>
#include <cuda_bf16.h>
#include <cstdint>
#include <math.h>

#define BATCH 8192
#define HID   1024
#define FOURH 4096
#define NLAYERS 4

// ---------------------------------------------------------------------------
// Scratch (allocation-free)
// ---------------------------------------------------------------------------
__device__ __nv_bfloat16 g_Ahi[(size_t)BATCH * HID];   // 16 MB
__device__ __nv_bfloat16 g_Alo[(size_t)BATCH * HID];   // 16 MB
__device__ __nv_bfloat16 g_Whi[(size_t)FOURH * HID];   // 8 MB (gate-permuted, transposed)
__device__ __nv_bfloat16 g_Wlo[(size_t)FOURH * HID];   // 8 MB

// ---------------------------------------------------------------------------
// PTX helpers (arch-agnostic: sm_80+)
// ---------------------------------------------------------------------------
__device__ __forceinline__ uint32_t smem_u32(const void* p) {
    uint32_t a;
    asm("{ .reg .u64 t; cvta.to.shared.u64 t, %1; cvt.u32.u64 %0, t; }" : "=r"(a) : "l"(p));
    return a;
}

__device__ __forceinline__ void cp_async16(uint32_t sdst, const void* gsrc) {
    asm volatile("cp.async.cg.shared.global [%0], [%1], 16;" :: "r"(sdst), "l"(gsrc));
}
__device__ __forceinline__ void cp_commit() {
    asm volatile("cp.async.commit_group;");
}
template <int N>
__device__ __forceinline__ void cp_wait() {
    asm volatile("cp.async.wait_group %0;" :: "n"(N));
}

__device__ __forceinline__ void ldm_x4(uint32_t* r, uint32_t addr) {
    asm volatile("ldmatrix.sync.aligned.m8n8.x4.shared.b16 {%0,%1,%2,%3}, [%4];"
                 : "=r"(r[0]), "=r"(r[1]), "=r"(r[2]), "=r"(r[3]) : "r"(addr));
}

__device__ __forceinline__ void mma16816(float* c, const uint32_t* a, const uint32_t* b) {
    asm volatile(
        "mma.sync.aligned.m16n8k16.row.col.f32.bf16.bf16.f32 "
        "{%0,%1,%2,%3}, {%4,%5,%6,%7}, {%8,%9}, {%0,%1,%2,%3};"
        : "+f"(c[0]), "+f"(c[1]), "+f"(c[2]), "+f"(c[3])
        : "r"(a[0]), "r"(a[1]), "r"(a[2]), "r"(a[3]), "r"(b[0]), "r"(b[1]));
}

// ---------------------------------------------------------------------------
// GEMM + fused LSTM gate epilogue (HMMA path)
// C[8192,4096] = A[8192,1024] @ W[4096,1024]^T with 3 split products.
// CTA tile 128x128, 8 warps (4 M x 2 N), warp tile 32x64.
// K staged in chunks of 32 bf16; 4 regions (Ahi,Alo,Whi,Wlo) double-buffered.
// smem row stride 40 bf16 (80 B) -> 16B-aligned, ldmatrix conflict-free.
// ---------------------------------------------------------------------------
#define KC        32                       // k per chunk (bf16 elems)
#define NCHUNKS   (HID / KC)               // 32
#define ROWB      80                       // smem bytes per row (32 elems + 8 pad)
#define REG_B     (128 * ROWB)             // 10240 B per region
#define STAGE_B   (4 * REG_B)              // 40960 B per buffer
#define GEMM_SMEM (2 * STAGE_B)            // 81920 B

__device__ __forceinline__ void load_region(const __nv_bfloat16* g, int row0, int k0,
                                            uint32_t sdst, int tid) {
    const int row  = tid >> 1;
    const int half = tid & 1;
    const __nv_bfloat16* src = g + (size_t)(row0 + row) * HID + k0 + half * 16;
    const uint32_t dst = sdst + (uint32_t)row * ROWB + half * 32;
    cp_async16(dst,      src);
    cp_async16(dst + 16, src + 8);
}

__global__ __launch_bounds__(256) void gemm_lstm_fused(
    const __nv_bfloat16* __restrict__ Ahi, const __nv_bfloat16* __restrict__ Alo,
    const __nv_bfloat16* __restrict__ Whi, const __nv_bfloat16* __restrict__ Wlo,
    const float* __restrict__ bias,       // [4H] original layout
    const float* __restrict__ rowx,       // [B] or nullptr (layer-0 x)
    const float* __restrict__ colw,       // [4H] or nullptr (layer-0 Wx0)
    const float* __restrict__ c_prev,     // [B,H]
    float* __restrict__ c_out,            // [B,H]
    float* __restrict__ h_out)            // [B,H]
{
    extern __shared__ char smem[];
    const uint32_t sb = smem_u32(smem);

    const int tid    = threadIdx.x;
    const int wid    = tid >> 5;
    const int lane   = tid & 31;
    const int warp_m = wid & 3;    // 0..3 -> 32-row slices
    const int warp_n = wid >> 2;   // 0..1 -> 64-col slices
    const int bm = blockIdx.y * 128;
    const int bn = blockIdx.x * 128;

    // ldmatrix lane-address components
    const uint32_t aLane = (uint32_t)(lane & 15) * ROWB + (uint32_t)(lane >> 4) * 16;
    const uint32_t bLane = (uint32_t)(((lane >> 4) << 3) | (lane & 7)) * ROWB
                         + (uint32_t)((lane >> 3) & 1) * 16;

    float acc[2][8][4];
    #pragma unroll
    for (int mt = 0; mt < 2; mt++)
        #pragma unroll
        for (int nt = 0; nt < 8; nt++)
            #pragma unroll
            for (int q = 0; q < 4; q++) acc[mt][nt][q] = 0.f;

    // ---- pipelined main loop over 32 k-chunks ----
    {
        const int k0 = 0;
        load_region(Ahi, bm, k0, sb + 0 * REG_B, tid);
        load_region(Alo, bm, k0, sb + 1 * REG_B, tid);
        load_region(Whi, bn, k0, sb + 2 * REG_B, tid);
        load_region(Wlo, bn, k0, sb + 3 * REG_B, tid);
        cp_commit();
    }

    for (int c = 0; c < NCHUNKS; ++c) {
        if (c + 1 < NCHUNKS) {
            const uint32_t sbuf = sb + ((c + 1) & 1) * STAGE_B;
            const int k0 = (c + 1) * KC;
            load_region(Ahi, bm, k0, sbuf + 0 * REG_B, tid);
            load_region(Alo, bm, k0, sbuf + 1 * REG_B, tid);
            load_region(Whi, bn, k0, sbuf + 2 * REG_B, tid);
            load_region(Wlo, bn, k0, sbuf + 3 * REG_B, tid);
            cp_commit();
            cp_wait<1>();
        } else {
            cp_wait<0>();
        }
        __syncthreads();

        const uint32_t base = sb + (c & 1) * STAGE_B;
        const uint32_t aBase = base + (uint32_t)warp_m * 32 * ROWB + aLane;
        const uint32_t bBase = base + (uint32_t)warp_n * 64 * ROWB + bLane;

        #pragma unroll
        for (int ks = 0; ks < 2; ks++) {
            const uint32_t ko = (uint32_t)ks * 32;   // 16 bf16 = 32 B

            uint32_t ah[2][4], bh[4][4];
            #pragma unroll
            for (int mt = 0; mt < 2; mt++)
                ldm_x4(ah[mt], aBase + 0 * REG_B + (uint32_t)mt * 16 * ROWB + ko);
            #pragma unroll
            for (int np = 0; np < 4; np++)
                ldm_x4(bh[np], bBase + 2 * REG_B + (uint32_t)np * 16 * ROWB + ko);

            #pragma unroll
            for (int mt = 0; mt < 2; mt++)
                #pragma unroll
                for (int nt = 0; nt < 8; nt++)
                    mma16816(acc[mt][nt], ah[mt], &bh[nt >> 1][(nt & 1) * 2]);

            uint32_t bl[4][4];
            #pragma unroll
            for (int np = 0; np < 4; np++)
                ldm_x4(bl[np], bBase + 3 * REG_B + (uint32_t)np * 16 * ROWB + ko);
            #pragma unroll
            for (int mt = 0; mt < 2; mt++)
                #pragma unroll
                for (int nt = 0; nt < 8; nt++)
                    mma16816(acc[mt][nt], ah[mt], &bl[nt >> 1][(nt & 1) * 2]);

            uint32_t al[2][4];
            #pragma unroll
            for (int mt = 0; mt < 2; mt++)
                ldm_x4(al[mt], aBase + 1 * REG_B + (uint32_t)mt * 16 * ROWB + ko);
            #pragma unroll
            for (int mt = 0; mt < 2; mt++)
                #pragma unroll
                for (int nt = 0; nt < 8; nt++)
                    mma16816(acc[mt][nt], al[mt], &bh[nt >> 1][(nt & 1) * 2]);
        }
        __syncthreads();
    }

    // ---- fused LSTM gate epilogue ----
    // acc C layout: c0,c1 -> (row = lane/4, n = 2*(lane%4)+{0,1}); c2,c3 -> row+8.
    // Permuted n: gate = n&3, hidden j = n>>2. Lane pair (even,odd) holds
    // (i,f)/(g,o) for the same j -> exchange via shfl.xor(1).
    const int quad = lane >> 2;
    const int glo  = lane & 1;          // 0: holds (i,f)   1: holds (g,o)
    const int joff = (lane >> 1) & 1;

    #pragma unroll
    for (int mt = 0; mt < 2; mt++) {
        const int rbase = bm + warp_m * 32 + mt * 16 + quad;
        #pragma unroll
        for (int nt = 0; nt < 8; nt++) {
            float v0 = acc[mt][nt][0], v1 = acc[mt][nt][1];
            float v2 = acc[mt][nt][2], v3 = acc[mt][nt][3];
            float r0 = __shfl_xor_sync(0xffffffffu, v0, 1);
            float r1 = __shfl_xor_sync(0xffffffffu, v1, 1);
            float r2 = __shfl_xor_sync(0xffffffffu, v2, 1);
            float r3 = __shfl_xor_sync(0xffffffffu, v3, 1);

            const int j = ((bn + warp_n * 64 + nt * 8) >> 2) + joff;
            int   m;
            float zi, zf, zg, zo;
            if (glo == 0) { m = rbase;     zi = v0; zf = v1; zg = r0; zo = r1; }
            else          { m = rbase + 8; zi = r2; zf = r3; zg = v2; zo = v3; }

            zi += bias[0 * HID + j];
            zf += bias[1 * HID + j];
            zg += bias[2 * HID + j];
            zo += bias[3 * HID + j];
            if (colw) {
                const float xv = rowx[m];
                zi = fmaf(xv, colw[0 * HID + j], zi);
                zf = fmaf(xv, colw[1 * HID + j], zf);
                zg = fmaf(xv, colw[2 * HID + j], zg);
                zo = fmaf(xv, colw[3 * HID + j], zo);
            }
            const float ig = 1.f / (1.f + expf(-zi));
            const float fg = 1.f / (1.f + expf(-zf));
            const float gg = tanhf(zg);
            const float og = 1.f / (1.f + expf(-zo));
            const float cc = fmaf(fg, c_prev[(size_t)m * HID + j], ig * gg);
            c_out[(size_t)m * HID + j] = cc;
            h_out[(size_t)m * HID + j] = og * tanhf(cc);
        }
    }
}

// ---------------------------------------------------------------------------
// Weight convert: transpose [1024,4096] -> [4096,1024], gate-permute rows,
// optional sum of two weights, split to bf16 hi/lo.
// ---------------------------------------------------------------------------
__global__ void conv_w(const float* __restrict__ Wa, const float* __restrict__ Wb,
                       __nv_bfloat16* __restrict__ hi, __nv_bfloat16* __restrict__ lo)
{
    __shared__ float s[32][33];
    const int k0 = blockIdx.x * 32, n0 = blockIdx.y * 32;
    const int tx = threadIdx.x, ty = threadIdx.y;
    const int n = n0 + tx;
    const int col = (n & 3) * HID + (n >> 2);
    float v = Wa[(size_t)(k0 + ty) * FOURH + col];
    if (Wb) v += Wb[(size_t)(k0 + ty) * FOURH + col];
    s[ty][tx] = v;
    __syncthreads();
    const float w = s[tx][ty];
    const __nv_bfloat16 h = __float2bfloat16(w);
    const float rem = w - __bfloat162float(h);
    const size_t o = (size_t)(n0 + ty) * HID + k0 + tx;
    hi[o] = h;
    lo[o] = __float2bfloat16(rem);
}

// ---------------------------------------------------------------------------
// Activation convert: fp32 -> bf16 hi/lo split (vectorized x4)
// ---------------------------------------------------------------------------
__global__ void conv_a(const float* __restrict__ x,
                       __nv_bfloat16* __restrict__ hi, __nv_bfloat16* __restrict__ lo)
{
    const size_t i = (size_t)blockIdx.x * blockDim.x + threadIdx.x;
    float4 v = ((const float4*)x)[i];
    float vs[4] = {v.x, v.y, v.z, v.w};
    uint32_t ph[2], pl[2];
    #pragma unroll
    for (int p = 0; p < 2; p++) {
        uint32_t h0, h1, l0, l1;
        {
            __nv_bfloat16 b = __float2bfloat16(vs[2 * p]);
            h0 = (uint32_t)__bfloat16_as_ushort(b);
            l0 = (uint32_t)__bfloat16_as_ushort(__float2bfloat16(vs[2 * p] - __bfloat162float(b)));
        }
        {
            __nv_bfloat16 b = __float2bfloat16(vs[2 * p + 1]);
            h1 = (uint32_t)__bfloat16_as_ushort(b);
            l1 = (uint32_t)__bfloat16_as_ushort(__float2bfloat16(vs[2 * p + 1] - __bfloat162float(b)));
        }
        ph[p] = h0 | (h1 << 16);
        pl[p] = l0 | (l1 << 16);
    }
    ((uint2*)hi)[i] = make_uint2(ph[0], ph[1]);
    ((uint2*)lo)[i] = make_uint2(pl[0], pl[1]);
}

// ---------------------------------------------------------------------------
// Head: pred[b] = dot(h[b,:], Wd) + bd
// ---------------------------------------------------------------------------
__global__ void head_kernel(const float* __restrict__ h, const float* __restrict__ Wd,
                            const float* __restrict__ bd, float* __restrict__ pred, int B)
{
    const int row  = blockIdx.x * (blockDim.x >> 5) + (threadIdx.x >> 5);
    const int lane = threadIdx.x & 31;
    if (row >= B) return;
    const float* hr = h + (size_t)row * HID;
    float s = 0.f;
    #pragma unroll 8
    for (int k = lane; k < HID; k += 32) s = fmaf(hr[k], Wd[k], s);
    #pragma unroll
    for (int off = 16; off; off >>= 1) s += __shfl_down_sync(0xffffffffu, s, off);
    if (lane == 0) pred[row] = s + bd[0];
}

// ---------------------------------------------------------------------------
extern "C" void kernel_launch(void* const* d_in, const int* in_sizes, int n_in,
                              void* d_out, int out_size)
{
    const float* x_todec = (const float*)d_in[0];
    const float* c0      = (const float*)d_in[1];
    const float* h0      = (const float*)d_in[2];
    const float* Wx0     = (const float*)d_in[3];
    const float* Wh0     = (const float*)d_in[4];
    const float* b0      = (const float*)d_in[5];
    const float* Wx      = (const float*)d_in[6];
    const float* Wh      = (const float*)d_in[7];
    const float* bl      = (const float*)d_in[8];
    const float* Wd      = (const float*)d_in[9];
    const float* bd      = (const float*)d_in[10];

    float* out  = (float*)d_out;
    float* cbuf = out;
    float* hbuf = out + (size_t)BATCH * HID;
    float* pred = out + 2 * (size_t)BATCH * HID;

    __nv_bfloat16 *Ahi, *Alo, *Whi, *Wlo;
    cudaGetSymbolAddress((void**)&Ahi, g_Ahi);
    cudaGetSymbolAddress((void**)&Alo, g_Alo);
    cudaGetSymbolAddress((void**)&Whi, g_Whi);
    cudaGetSymbolAddress((void**)&Wlo, g_Wlo);

    static bool attr_set = false;
    if (!attr_set) {
        cudaFuncSetAttribute(gemm_lstm_fused,
                             cudaFuncAttributeMaxDynamicSharedMemorySize, GEMM_SMEM);
        attr_set = true;
    }

    const dim3 wgrid(HID / 32, FOURH / 32);       // (32,128)
    const dim3 wblk(32, 32);
    const int  ablocks = (BATCH * HID / 4) / 256; // 8192
    const dim3 ggrid(FOURH / 128, BATCH / 128);   // (32,64)

    // ---- layer 0: z = h0 @ Wh0^T (+ x*Wx0 + b0 in epilogue) ----
    conv_w<<<wgrid, wblk>>>(Wh0, nullptr, Whi, Wlo);
    conv_a<<<ablocks, 256>>>(h0, Ahi, Alo);
    gemm_lstm_fused<<<ggrid, 256, GEMM_SMEM>>>(Ahi, Alo, Whi, Wlo,
                                               b0, x_todec, Wx0, c0, cbuf, hbuf);

    // ---- layers 1..3: z = h @ (Wx[l]+Wh[l])^T + b[l] ----
    for (int l = 0; l < NLAYERS - 1; l++) {
        const size_t woff = (size_t)l * HID * FOURH;
        conv_w<<<wgrid, wblk>>>(Wx + woff, Wh + woff, Whi, Wlo);
        conv_a<<<ablocks, 256>>>(hbuf, Ahi, Alo);
        gemm_lstm_fused<<<ggrid, 256, GEMM_SMEM>>>(Ahi, Alo, Whi, Wlo,
                                                   bl + (size_t)l * FOURH,
                                                   nullptr, nullptr, cbuf, cbuf, hbuf);
    }

    head_kernel<<<BATCH / 8, 256>>>(hbuf, Wd, bd, pred, BATCH);
}

// round 5
// speedup vs baseline: 2.1963x; 1.4339x over previous
#include <cuda_runtime.h>
#include <cuda_fp16.h>
#include <cstdint>
#include <math.h>

#define BATCH 8192
#define HID   1024
#define FOURH 4096
#define NLAYERS 4

// ---------------------------------------------------------------------------
// Scratch (allocation-free). Ping-pong activation splits to avoid the
// cross-CTA race of writing the GEMM's own input operand.
// ---------------------------------------------------------------------------
__device__ __half g_Ah0[(size_t)BATCH * HID];                // 16 MB
__device__ __half g_Al0[(size_t)BATCH * HID];                // 16 MB
__device__ __half g_Ah1[(size_t)BATCH * HID];                // 16 MB
__device__ __half g_Al1[(size_t)BATCH * HID];                // 16 MB
__device__ __half g_W16[(size_t)NLAYERS * FOURH * HID];      // 32 MB (gate-permuted, transposed)

// ---------------------------------------------------------------------------
// PTX helpers (arch-agnostic: sm_80+)
// ---------------------------------------------------------------------------
__device__ __forceinline__ uint32_t smem_u32(const void* p) {
    uint32_t a;
    asm("{ .reg .u64 t; cvta.to.shared.u64 t, %1; cvt.u32.u64 %0, t; }" : "=r"(a) : "l"(p));
    return a;
}
__device__ __forceinline__ void cp_async16(uint32_t sdst, const void* gsrc) {
    asm volatile("cp.async.cg.shared.global [%0], [%1], 16;" :: "r"(sdst), "l"(gsrc));
}
__device__ __forceinline__ void cp_commit() { asm volatile("cp.async.commit_group;"); }
template <int N>
__device__ __forceinline__ void cp_wait() { asm volatile("cp.async.wait_group %0;" :: "n"(N)); }

__device__ __forceinline__ void ldm_x4(uint32_t* r, uint32_t addr) {
    asm volatile("ldmatrix.sync.aligned.m8n8.x4.shared.b16 {%0,%1,%2,%3}, [%4];"
                 : "=r"(r[0]), "=r"(r[1]), "=r"(r[2]), "=r"(r[3]) : "r"(addr));
}
__device__ __forceinline__ void mma16816(float* c, const uint32_t* a, const uint32_t* b) {
    asm volatile(
        "mma.sync.aligned.m16n8k16.row.col.f32.f16.f16.f32 "
        "{%0,%1,%2,%3}, {%4,%5,%6,%7}, {%8,%9}, {%0,%1,%2,%3};"
        : "+f"(c[0]), "+f"(c[1]), "+f"(c[2]), "+f"(c[3])
        : "r"(a[0]), "r"(a[1]), "r"(a[2]), "r"(a[3]), "r"(b[0]), "r"(b[1]));
}

// ---------------------------------------------------------------------------
// GEMM + fused LSTM gate epilogue + fused next-layer fp16 split (ping-pong).
// C[8192,4096] = (Ah+Al)[8192,1024] @ W16[4096,1024]^T   (2 HMMA products)
// CTA tile 128x128, 8 warps (4 M x 2 N), warp tile 32x64.
// K chunks of 64 fp16; regions Ah, Al, Wh double-buffered.
// ROWB=144 (128B data + 16 pad): 144*r mod 128 = 16r -> ldmatrix conflict-free.
// ---------------------------------------------------------------------------
#define KC        64
#define NCHUNKS   (HID / KC)               // 16
#define ROWB      144
#define REG_B     (128 * ROWB)             // 18432 B
#define STAGE_B   (3 * REG_B)              // 55296 B
#define GEMM_SMEM (2 * STAGE_B)            // 110592 B

__device__ __forceinline__ void load_region(const __half* g, int row0, int k0,
                                            uint32_t sdst, int tid) {
    const int row  = tid >> 1;
    const int half = tid & 1;
    const __half* src = g + (size_t)(row0 + row) * HID + k0 + half * 32;
    const uint32_t dst = sdst + (uint32_t)row * ROWB + half * 64;
    #pragma unroll
    for (int q = 0; q < 4; q++)
        cp_async16(dst + q * 16, src + q * 8);
}

__global__ __launch_bounds__(256) void gemm_lstm_fused(
    const __half* __restrict__ Ah, const __half* __restrict__ Al,
    const __half* __restrict__ Wh,
    const float* __restrict__ bias,       // [4H] original layout
    const float* __restrict__ rowx,       // [B] or nullptr (layer-0 x)
    const float* __restrict__ colw,       // [4H] or nullptr (layer-0 Wx0)
    const float* __restrict__ c_prev,     // [B,H]
    float* __restrict__ c_out,            // [B,H]
    float* __restrict__ h_out,            // [B,H]
    __half* __restrict__ nAh,             // next-layer A hi split (ping-pong buf)
    __half* __restrict__ nAl)             // next-layer A lo split
{
    extern __shared__ char smem[];
    const uint32_t sb = smem_u32(smem);

    const int tid    = threadIdx.x;
    const int wid    = tid >> 5;
    const int lane   = tid & 31;
    const int warp_m = wid & 3;
    const int warp_n = wid >> 2;
    const int bm = blockIdx.y * 128;
    const int bn = blockIdx.x * 128;

    const uint32_t aLane = (uint32_t)(lane & 15) * ROWB + (uint32_t)(lane >> 4) * 16;
    const uint32_t bLane = (uint32_t)(((lane >> 4) << 3) | (lane & 7)) * ROWB
                         + (uint32_t)((lane >> 3) & 1) * 16;

    float acc[2][8][4];
    #pragma unroll
    for (int mt = 0; mt < 2; mt++)
        #pragma unroll
        for (int nt = 0; nt < 8; nt++)
            #pragma unroll
            for (int q = 0; q < 4; q++) acc[mt][nt][q] = 0.f;

    load_region(Ah, bm, 0, sb + 0 * REG_B, tid);
    load_region(Al, bm, 0, sb + 1 * REG_B, tid);
    load_region(Wh, bn, 0, sb + 2 * REG_B, tid);
    cp_commit();

    for (int c = 0; c < NCHUNKS; ++c) {
        if (c + 1 < NCHUNKS) {
            const uint32_t sbuf = sb + ((c + 1) & 1) * STAGE_B;
            const int k0 = (c + 1) * KC;
            load_region(Ah, bm, k0, sbuf + 0 * REG_B, tid);
            load_region(Al, bm, k0, sbuf + 1 * REG_B, tid);
            load_region(Wh, bn, k0, sbuf + 2 * REG_B, tid);
            cp_commit();
            cp_wait<1>();
        } else {
            cp_wait<0>();
        }
        __syncthreads();

        const uint32_t base  = sb + (c & 1) * STAGE_B;
        const uint32_t aBase = base + (uint32_t)warp_m * 32 * ROWB + aLane;
        const uint32_t bBase = base + (uint32_t)warp_n * 64 * ROWB + bLane;

        #pragma unroll
        for (int ks = 0; ks < 4; ks++) {
            const uint32_t ko = (uint32_t)ks * 32;   // 16 fp16 = 32 B

            uint32_t ah[2][4], al[2][4], bh[4][4];
            #pragma unroll
            for (int np = 0; np < 4; np++)
                ldm_x4(bh[np], bBase + 2 * REG_B + (uint32_t)np * 16 * ROWB + ko);
            #pragma unroll
            for (int mt = 0; mt < 2; mt++)
                ldm_x4(ah[mt], aBase + 0 * REG_B + (uint32_t)mt * 16 * ROWB + ko);

            #pragma unroll
            for (int mt = 0; mt < 2; mt++)
                #pragma unroll
                for (int nt = 0; nt < 8; nt++)
                    mma16816(acc[mt][nt], ah[mt], &bh[nt >> 1][(nt & 1) * 2]);

            #pragma unroll
            for (int mt = 0; mt < 2; mt++)
                ldm_x4(al[mt], aBase + 1 * REG_B + (uint32_t)mt * 16 * ROWB + ko);
            #pragma unroll
            for (int mt = 0; mt < 2; mt++)
                #pragma unroll
                for (int nt = 0; nt < 8; nt++)
                    mma16816(acc[mt][nt], al[mt], &bh[nt >> 1][(nt & 1) * 2]);
        }
        __syncthreads();
    }

    // ---- fused LSTM gate epilogue ----
    const int quad = lane >> 2;
    const int glo  = lane & 1;
    const int joff = (lane >> 1) & 1;

    #pragma unroll
    for (int mt = 0; mt < 2; mt++) {
        const int rbase = bm + warp_m * 32 + mt * 16 + quad;
        #pragma unroll
        for (int nt = 0; nt < 8; nt++) {
            float v0 = acc[mt][nt][0], v1 = acc[mt][nt][1];
            float v2 = acc[mt][nt][2], v3 = acc[mt][nt][3];
            float r0 = __shfl_xor_sync(0xffffffffu, v0, 1);
            float r1 = __shfl_xor_sync(0xffffffffu, v1, 1);
            float r2 = __shfl_xor_sync(0xffffffffu, v2, 1);
            float r3 = __shfl_xor_sync(0xffffffffu, v3, 1);

            const int j = ((bn + warp_n * 64 + nt * 8) >> 2) + joff;
            int   m;
            float zi, zf, zg, zo;
            if (glo == 0) { m = rbase;     zi = v0; zf = v1; zg = r0; zo = r1; }
            else          { m = rbase + 8; zi = r2; zf = r3; zg = v2; zo = v3; }

            zi += bias[0 * HID + j];
            zf += bias[1 * HID + j];
            zg += bias[2 * HID + j];
            zo += bias[3 * HID + j];
            if (colw) {
                const float xv = rowx[m];
                zi = fmaf(xv, colw[0 * HID + j], zi);
                zf = fmaf(xv, colw[1 * HID + j], zf);
                zg = fmaf(xv, colw[2 * HID + j], zg);
                zo = fmaf(xv, colw[3 * HID + j], zo);
            }
            const float ig = 1.f / (1.f + expf(-zi));
            const float fg = 1.f / (1.f + expf(-zf));
            const float gg = tanhf(zg);
            const float og = 1.f / (1.f + expf(-zo));
            const size_t idx = (size_t)m * HID + j;
            const float cc = fmaf(fg, c_prev[idx], ig * gg);
            const float hh = og * tanhf(cc);
            c_out[idx] = cc;
            h_out[idx] = hh;
            const __half h_hi = __float2half_rn(hh);
            nAh[idx] = h_hi;
            nAl[idx] = __float2half_rn(hh - __half2float(h_hi));
        }
    }
}

// ---------------------------------------------------------------------------
// Weight prep (ALL layers, one launch): transpose [1024,4096] -> [4096,1024],
// gate-permute rows, sum Wx+Wh for layers>=1, convert to fp16.
// ---------------------------------------------------------------------------
__global__ void wprep(const float* __restrict__ Wh0,
                      const float* __restrict__ Wx, const float* __restrict__ Whh,
                      __half* __restrict__ out)
{
    __shared__ float s[32][33];
    const int l  = blockIdx.z;
    const int k0 = blockIdx.x * 32, n0 = blockIdx.y * 32;
    const int tx = threadIdx.x, ty = threadIdx.y;
    const int n = n0 + tx;
    const int col = (n & 3) * HID + (n >> 2);
    float v;
    if (l == 0) {
        v = Wh0[(size_t)(k0 + ty) * FOURH + col];
    } else {
        const size_t off = (size_t)(l - 1) * HID * FOURH + (size_t)(k0 + ty) * FOURH + col;
        v = Wx[off] + Whh[off];
    }
    s[ty][tx] = v;
    __syncthreads();
    out[(size_t)l * FOURH * HID + (size_t)(n0 + ty) * HID + k0 + tx] =
        __float2half_rn(s[tx][ty]);
}

// ---------------------------------------------------------------------------
// h0 fp32 -> fp16 hi/lo split (vectorized x4)
// ---------------------------------------------------------------------------
__global__ void conv_a(const float* __restrict__ x,
                       __half* __restrict__ hi, __half* __restrict__ lo)
{
    const size_t i = (size_t)blockIdx.x * blockDim.x + threadIdx.x;
    float4 v = ((const float4*)x)[i];
    float vs[4] = {v.x, v.y, v.z, v.w};
    uint32_t ph[2], pl[2];
    #pragma unroll
    for (int p = 0; p < 2; p++) {
        uint32_t hw[2], lw[2];
        #pragma unroll
        for (int q = 0; q < 2; q++) {
            const float x0 = vs[2 * p + q];
            const __half hh = __float2half_rn(x0);
            hw[q] = (uint32_t)__half_as_ushort(hh);
            lw[q] = (uint32_t)__half_as_ushort(__float2half_rn(x0 - __half2float(hh)));
        }
        ph[p] = hw[0] | (hw[1] << 16);
        pl[p] = lw[0] | (lw[1] << 16);
    }
    ((uint2*)hi)[i] = make_uint2(ph[0], ph[1]);
    ((uint2*)lo)[i] = make_uint2(pl[0], pl[1]);
}

// ---------------------------------------------------------------------------
// Head: pred[b] = dot(h[b,:], Wd) + bd
// ---------------------------------------------------------------------------
__global__ void head_kernel(const float* __restrict__ h, const float* __restrict__ Wd,
                            const float* __restrict__ bd, float* __restrict__ pred, int B)
{
    const int row  = blockIdx.x * (blockDim.x >> 5) + (threadIdx.x >> 5);
    const int lane = threadIdx.x & 31;
    if (row >= B) return;
    const float* hr = h + (size_t)row * HID;
    float s = 0.f;
    #pragma unroll 8
    for (int k = lane; k < HID; k += 32) s = fmaf(hr[k], Wd[k], s);
    #pragma unroll
    for (int off = 16; off; off >>= 1) s += __shfl_down_sync(0xffffffffu, s, off);
    if (lane == 0) pred[row] = s + bd[0];
}

// ---------------------------------------------------------------------------
extern "C" void kernel_launch(void* const* d_in, const int* in_sizes, int n_in,
                              void* d_out, int out_size)
{
    const float* x_todec = (const float*)d_in[0];
    const float* c0      = (const float*)d_in[1];
    const float* h0      = (const float*)d_in[2];
    const float* Wx0     = (const float*)d_in[3];
    const float* Wh0     = (const float*)d_in[4];
    const float* b0      = (const float*)d_in[5];
    const float* Wx      = (const float*)d_in[6];
    const float* Wh      = (const float*)d_in[7];
    const float* bl      = (const float*)d_in[8];
    const float* Wd      = (const float*)d_in[9];
    const float* bd      = (const float*)d_in[10];

    float* out  = (float*)d_out;
    float* cbuf = out;
    float* hbuf = out + (size_t)BATCH * HID;
    float* pred = out + 2 * (size_t)BATCH * HID;

    __half *A0h, *A0l, *A1h, *A1l, *W16;
    cudaGetSymbolAddress((void**)&A0h, g_Ah0);
    cudaGetSymbolAddress((void**)&A0l, g_Al0);
    cudaGetSymbolAddress((void**)&A1h, g_Ah1);
    cudaGetSymbolAddress((void**)&A1l, g_Al1);
    cudaGetSymbolAddress((void**)&W16, g_W16);

    static bool attr_set = false;
    if (!attr_set) {
        cudaFuncSetAttribute(gemm_lstm_fused,
                             cudaFuncAttributeMaxDynamicSharedMemorySize, GEMM_SMEM);
        attr_set = true;
    }

    const dim3 ggrid(FOURH / 128, BATCH / 128);   // (32,64)

    // All weight conversion up-front (independent of activations)
    wprep<<<dim3(HID / 32, FOURH / 32, NLAYERS), dim3(32, 32)>>>(Wh0, Wx, Wh, W16);
    conv_a<<<(BATCH * HID / 4) / 256, 256>>>(h0, A0h, A0l);

    // Ping-pong activation splits across layers (write != read buffer)
    __half* curh = A0h; __half* curl = A0l;
    __half* nxth = A1h; __half* nxtl = A1l;

    // layer 0: z = h0 @ Wh0^T (+ x*Wx0 + b0 in epilogue)
    gemm_lstm_fused<<<ggrid, 256, GEMM_SMEM>>>(curh, curl, W16,
                                               b0, x_todec, Wx0,
                                               c0, cbuf, hbuf, nxth, nxtl);
    // layers 1..3: z = h @ (Wx+Wh)^T + b
    for (int l = 1; l < NLAYERS; l++) {
        __half* th = curh; __half* tl = curl;
        curh = nxth; curl = nxtl;
        nxth = th;   nxtl = tl;
        gemm_lstm_fused<<<ggrid, 256, GEMM_SMEM>>>(curh, curl,
                                                   W16 + (size_t)l * FOURH * HID,
                                                   bl + (size_t)(l - 1) * FOURH,
                                                   nullptr, nullptr,
                                                   cbuf, cbuf, hbuf, nxth, nxtl);
    }

    head_kernel<<<BATCH / 8, 256>>>(hbuf, Wd, bd, pred, BATCH);
}

// round 7
// speedup vs baseline: 3.1455x; 1.4321x over previous
#include <cuda_runtime.h>
#include <cuda_fp16.h>
#include <cstdint>
#include <math.h>

#define BATCH 8192
#define HID   1024
#define FOURH 4096
#define NLAYERS 4

// ---------------------------------------------------------------------------
// Scratch (allocation-free). Ping-pong activation splits (cross-CTA safety).
// ---------------------------------------------------------------------------
__device__ __half g_Ah0[(size_t)BATCH * HID];
__device__ __half g_Al0[(size_t)BATCH * HID];
__device__ __half g_Ah1[(size_t)BATCH * HID];
__device__ __half g_Al1[(size_t)BATCH * HID];
__device__ __half g_W16[(size_t)NLAYERS * FOURH * HID];   // gate-permuted, transposed

// ---------------------------------------------------------------------------
// PTX helpers (arch-agnostic: sm_80+)
// ---------------------------------------------------------------------------
__device__ __forceinline__ uint32_t smem_u32(const void* p) {
    uint32_t a;
    asm("{ .reg .u64 t; cvta.to.shared.u64 t, %1; cvt.u32.u64 %0, t; }" : "=r"(a) : "l"(p));
    return a;
}
__device__ __forceinline__ void cp_async16(uint32_t sdst, const void* gsrc) {
    asm volatile("cp.async.cg.shared.global [%0], [%1], 16;" :: "r"(sdst), "l"(gsrc));
}
__device__ __forceinline__ void cp_commit() { asm volatile("cp.async.commit_group;"); }
template <int N>
__device__ __forceinline__ void cp_wait() { asm volatile("cp.async.wait_group %0;" :: "n"(N)); }

__device__ __forceinline__ void ldm_x4(uint32_t* r, uint32_t addr) {
    asm volatile("ldmatrix.sync.aligned.m8n8.x4.shared.b16 {%0,%1,%2,%3}, [%4];"
                 : "=r"(r[0]), "=r"(r[1]), "=r"(r[2]), "=r"(r[3]) : "r"(addr));
}
__device__ __forceinline__ void mma16816(float* c, const uint32_t* a, const uint32_t* b) {
    asm volatile(
        "mma.sync.aligned.m16n8k16.row.col.f32.f16.f16.f32 "
        "{%0,%1,%2,%3}, {%4,%5,%6,%7}, {%8,%9}, {%0,%1,%2,%3};"
        : "+f"(c[0]), "+f"(c[1]), "+f"(c[2]), "+f"(c[3])
        : "r"(a[0]), "r"(a[1]), "r"(a[2]), "r"(a[3]), "r"(b[0]), "r"(b[1]));
}

// ---------------------------------------------------------------------------
// GEMM + fused LSTM gate epilogue + fused next-layer fp16 split.
// C = (Ah+Al) @ W16^T, 2 HMMA products. CTA tile 128x128, 8 warps (4Mx2N),
// warp tile 32x64. K chunks of 32 fp16, double-buffered; 2 CTAs/SM.
// ROWB=80: r*80 mod 128 = {0,80,32,112,64,16,96,48} -> ldmatrix conflict-free.
// ---------------------------------------------------------------------------
#define KC        32
#define NCHUNKS   (HID / KC)               // 32
#define ROWB      80
#define REG_B     (128 * ROWB)             // 10240 B
#define STAGE_B   (3 * REG_B)              // 30720 B
#define GEMM_SMEM (2 * STAGE_B)            // 61440 B -> 2 CTAs/SM

__device__ __forceinline__ void load_region(const __half* g, int row0, int k0,
                                            uint32_t sdst, int tid) {
    const int row  = tid >> 1;
    const int half = tid & 1;
    const __half* src = g + (size_t)(row0 + row) * HID + k0 + half * 16;
    const uint32_t dst = sdst + (uint32_t)row * ROWB + half * 32;
    cp_async16(dst,      src);
    cp_async16(dst + 16, src + 8);
}

__global__ __launch_bounds__(256, 2) void gemm_lstm_fused(
    const __half* __restrict__ Ah, const __half* __restrict__ Al,
    const __half* __restrict__ Wh,
    const float* __restrict__ bias,       // [4H] original layout
    const float* __restrict__ rowx,       // [B] or nullptr (layer-0 x)
    const float* __restrict__ colw,       // [4H] or nullptr (layer-0 Wx0)
    const float* __restrict__ c_prev,     // [B,H]
    float* __restrict__ c_out,            // [B,H]
    float* __restrict__ h_out,            // [B,H]
    __half* __restrict__ nAh,             // next-layer A hi split (ping-pong)
    __half* __restrict__ nAl)
{
    extern __shared__ char smem[];
    const uint32_t sb = smem_u32(smem);

    const int tid    = threadIdx.x;
    const int wid    = tid >> 5;
    const int lane   = tid & 31;
    const int warp_m = wid & 3;
    const int warp_n = wid >> 2;
    const int bm = blockIdx.y * 128;
    const int bn = blockIdx.x * 128;

    const uint32_t aLane = (uint32_t)(lane & 15) * ROWB + (uint32_t)(lane >> 4) * 16;
    const uint32_t bLane = (uint32_t)(((lane >> 4) << 3) | (lane & 7)) * ROWB
                         + (uint32_t)((lane >> 3) & 1) * 16;

    float acc[2][8][4];
    #pragma unroll
    for (int mt = 0; mt < 2; mt++)
        #pragma unroll
        for (int nt = 0; nt < 8; nt++)
            #pragma unroll
            for (int q = 0; q < 4; q++) acc[mt][nt][q] = 0.f;

    load_region(Ah, bm, 0, sb + 0 * REG_B, tid);
    load_region(Al, bm, 0, sb + 1 * REG_B, tid);
    load_region(Wh, bn, 0, sb + 2 * REG_B, tid);
    cp_commit();

    for (int c = 0; c < NCHUNKS; ++c) {
        if (c + 1 < NCHUNKS) {
            const uint32_t sbuf = sb + ((c + 1) & 1) * STAGE_B;
            const int k0 = (c + 1) * KC;
            load_region(Ah, bm, k0, sbuf + 0 * REG_B, tid);
            load_region(Al, bm, k0, sbuf + 1 * REG_B, tid);
            load_region(Wh, bn, k0, sbuf + 2 * REG_B, tid);
            cp_commit();
            cp_wait<1>();
        } else {
            cp_wait<0>();
        }
        __syncthreads();

        const uint32_t base  = sb + (c & 1) * STAGE_B;
        const uint32_t aBase = base + (uint32_t)warp_m * 32 * ROWB + aLane;
        const uint32_t bBase = base + (uint32_t)warp_n * 64 * ROWB + bLane;

        #pragma unroll
        for (int ks = 0; ks < 2; ks++) {
            const uint32_t ko = (uint32_t)ks * 32;   // 16 fp16 = 32 B

            uint32_t ah[2][4], al[2][4], bh[4][4];
            #pragma unroll
            for (int np = 0; np < 4; np++)
                ldm_x4(bh[np], bBase + 2 * REG_B + (uint32_t)np * 16 * ROWB + ko);
            #pragma unroll
            for (int mt = 0; mt < 2; mt++)
                ldm_x4(ah[mt], aBase + 0 * REG_B + (uint32_t)mt * 16 * ROWB + ko);

            #pragma unroll
            for (int mt = 0; mt < 2; mt++)
                #pragma unroll
                for (int nt = 0; nt < 8; nt++)
                    mma16816(acc[mt][nt], ah[mt], &bh[nt >> 1][(nt & 1) * 2]);

            #pragma unroll
            for (int mt = 0; mt < 2; mt++)
                ldm_x4(al[mt], aBase + 1 * REG_B + (uint32_t)mt * 16 * ROWB + ko);
            #pragma unroll
            for (int mt = 0; mt < 2; mt++)
                #pragma unroll
                for (int nt = 0; nt < 8; nt++)
                    mma16816(acc[mt][nt], al[mt], &bh[nt >> 1][(nt & 1) * 2]);
        }
        __syncthreads();
    }

    // ---- fused LSTM gate epilogue ----
    const int quad = lane >> 2;
    const int glo  = lane & 1;
    const int joff = (lane >> 1) & 1;

    #pragma unroll
    for (int mt = 0; mt < 2; mt++) {
        const int rbase = bm + warp_m * 32 + mt * 16 + quad;
        #pragma unroll
        for (int nt = 0; nt < 8; nt++) {
            float v0 = acc[mt][nt][0], v1 = acc[mt][nt][1];
            float v2 = acc[mt][nt][2], v3 = acc[mt][nt][3];
            float r0 = __shfl_xor_sync(0xffffffffu, v0, 1);
            float r1 = __shfl_xor_sync(0xffffffffu, v1, 1);
            float r2 = __shfl_xor_sync(0xffffffffu, v2, 1);
            float r3 = __shfl_xor_sync(0xffffffffu, v3, 1);

            const int j = ((bn + warp_n * 64 + nt * 8) >> 2) + joff;
            int   m;
            float zi, zf, zg, zo;
            if (glo == 0) { m = rbase;     zi = v0; zf = v1; zg = r0; zo = r1; }
            else          { m = rbase + 8; zi = r2; zf = r3; zg = v2; zo = v3; }

            zi += bias[0 * HID + j];
            zf += bias[1 * HID + j];
            zg += bias[2 * HID + j];
            zo += bias[3 * HID + j];
            if (colw) {
                const float xv = rowx[m];
                zi = fmaf(xv, colw[0 * HID + j], zi);
                zf = fmaf(xv, colw[1 * HID + j], zf);
                zg = fmaf(xv, colw[2 * HID + j], zg);
                zo = fmaf(xv, colw[3 * HID + j], zo);
            }
            const float ig = 1.f / (1.f + expf(-zi));
            const float fg = 1.f / (1.f + expf(-zf));
            const float gg = tanhf(zg);
            const float og = 1.f / (1.f + expf(-zo));
            const size_t idx = (size_t)m * HID + j;
            const float cc = fmaf(fg, c_prev[idx], ig * gg);
            const float hh = og * tanhf(cc);
            c_out[idx] = cc;
            h_out[idx] = hh;
            const __half h_hi = __float2half_rn(hh);
            nAh[idx] = h_hi;
            nAl[idx] = __float2half_rn(hh - __half2float(h_hi));
        }
    }
}

// ---------------------------------------------------------------------------
// Weight prep (ALL layers, one launch): transpose, gate-permute, sum, fp16.
// ---------------------------------------------------------------------------
__global__ void wprep(const float* __restrict__ Wh0,
                      const float* __restrict__ Wx, const float* __restrict__ Whh,
                      __half* __restrict__ out)
{
    __shared__ float s[32][33];
    const int l  = blockIdx.z;
    const int k0 = blockIdx.x * 32, n0 = blockIdx.y * 32;
    const int tx = threadIdx.x, ty = threadIdx.y;
    const int n = n0 + tx;
    const int col = (n & 3) * HID + (n >> 2);
    float v;
    if (l == 0) {
        v = Wh0[(size_t)(k0 + ty) * FOURH + col];
    } else {
        const size_t off = (size_t)(l - 1) * HID * FOURH + (size_t)(k0 + ty) * FOURH + col;
        v = Wx[off] + Whh[off];
    }
    s[ty][tx] = v;
    __syncthreads();
    out[(size_t)l * FOURH * HID + (size_t)(n0 + ty) * HID + k0 + tx] =
        __float2half_rn(s[tx][ty]);
}

// ---------------------------------------------------------------------------
// h0 fp32 -> fp16 hi/lo split (vectorized x4)
// ---------------------------------------------------------------------------
__global__ void conv_a(const float* __restrict__ x,
                       __half* __restrict__ hi, __half* __restrict__ lo)
{
    const size_t i = (size_t)blockIdx.x * blockDim.x + threadIdx.x;
    float4 v = ((const float4*)x)[i];
    float vs[4] = {v.x, v.y, v.z, v.w};
    uint32_t ph[2], pl[2];
    #pragma unroll
    for (int p = 0; p < 2; p++) {
        uint32_t hw[2], lw[2];
        #pragma unroll
        for (int q = 0; q < 2; q++) {
            const float x0 = vs[2 * p + q];
            const __half hh = __float2half_rn(x0);
            hw[q] = (uint32_t)__half_as_ushort(hh);
            lw[q] = (uint32_t)__half_as_ushort(__float2half_rn(x0 - __half2float(hh)));
        }
        ph[p] = hw[0] | (hw[1] << 16);
        pl[p] = lw[0] | (lw[1] << 16);
    }
    ((uint2*)hi)[i] = make_uint2(ph[0], ph[1]);
    ((uint2*)lo)[i] = make_uint2(pl[0], pl[1]);
}

// ---------------------------------------------------------------------------
// Head: pred[b] = dot(h[b,:], Wd) + bd
// ---------------------------------------------------------------------------
__global__ void head_kernel(const float* __restrict__ h, const float* __restrict__ Wd,
                            const float* __restrict__ bd, float* __restrict__ pred, int B)
{
    const int row  = blockIdx.x * (blockDim.x >> 5) + (threadIdx.x >> 5);
    const int lane = threadIdx.x & 31;
    if (row >= B) return;
    const float* hr = h + (size_t)row * HID;
    float s = 0.f;
    #pragma unroll 8
    for (int k = lane; k < HID; k += 32) s = fmaf(hr[k], Wd[k], s);
    #pragma unroll
    for (int off = 16; off; off >>= 1) s += __shfl_down_sync(0xffffffffu, s, off);
    if (lane == 0) pred[row] = s + bd[0];
}

// ---------------------------------------------------------------------------
extern "C" void kernel_launch(void* const* d_in, const int* in_sizes, int n_in,
                              void* d_out, int out_size)
{
    const float* x_todec = (const float*)d_in[0];
    const float* c0      = (const float*)d_in[1];
    const float* h0      = (const float*)d_in[2];
    const float* Wx0     = (const float*)d_in[3];
    const float* Wh0     = (const float*)d_in[4];
    const float* b0      = (const float*)d_in[5];
    const float* Wx      = (const float*)d_in[6];
    const float* Wh      = (const float*)d_in[7];
    const float* bl      = (const float*)d_in[8];
    const float* Wd      = (const float*)d_in[9];
    const float* bd      = (const float*)d_in[10];

    float* out  = (float*)d_out;
    float* cbuf = out;
    float* hbuf = out + (size_t)BATCH * HID;
    float* pred = out + 2 * (size_t)BATCH * HID;

    __half *A0h, *A0l, *A1h, *A1l, *W16;
    cudaGetSymbolAddress((void**)&A0h, g_Ah0);
    cudaGetSymbolAddress((void**)&A0l, g_Al0);
    cudaGetSymbolAddress((void**)&A1h, g_Ah1);
    cudaGetSymbolAddress((void**)&A1l, g_Al1);
    cudaGetSymbolAddress((void**)&W16, g_W16);

    static bool attr_set = false;
    if (!attr_set) {
        cudaFuncSetAttribute(gemm_lstm_fused,
                             cudaFuncAttributeMaxDynamicSharedMemorySize, GEMM_SMEM);
        attr_set = true;
    }

    const dim3 ggrid(FOURH / 128, BATCH / 128);   // (32,64)

    wprep<<<dim3(HID / 32, FOURH / 32, NLAYERS), dim3(32, 32)>>>(Wh0, Wx, Wh, W16);
    conv_a<<<(BATCH * HID / 4) / 256, 256>>>(h0, A0h, A0l);

    __half* curh = A0h; __half* curl = A0l;
    __half* nxth = A1h; __half* nxtl = A1l;

    // layer 0: z = h0 @ Wh0^T (+ x*Wx0 + b0 in epilogue)
    gemm_lstm_fused<<<ggrid, 256, GEMM_SMEM>>>(curh, curl, W16,
                                               b0, x_todec, Wx0,
                                               c0, cbuf, hbuf, nxth, nxtl);
    // layers 1..3: z = h @ (Wx+Wh)^T + b
    for (int l = 1; l < NLAYERS; l++) {
        __half* th = curh; __half* tl = curl;
        curh = nxth; curl = nxtl;
        nxth = th;   nxtl = tl;
        gemm_lstm_fused<<<ggrid, 256, GEMM_SMEM>>>(curh, curl,
                                                   W16 + (size_t)l * FOURH * HID,
                                                   bl + (size_t)(l - 1) * FOURH,
                                                   nullptr, nullptr,
                                                   cbuf, cbuf, hbuf, nxth, nxtl);
    }

    head_kernel<<<BATCH / 8, 256>>>(hbuf, Wd, bd, pred, BATCH);
}

// round 8
// speedup vs baseline: 3.2789x; 1.0424x over previous
#include <cuda_runtime.h>
#include <cuda_fp16.h>
#include <cstdint>
#include <math.h>

#define BATCH 8192
#define HID   1024
#define FOURH 4096
#define NLAYERS 4

// ---------------------------------------------------------------------------
// Scratch (allocation-free). Ping-pong activation splits (cross-CTA safety).
// ---------------------------------------------------------------------------
__device__ __half g_Ah0[(size_t)BATCH * HID];
__device__ __half g_Al0[(size_t)BATCH * HID];
__device__ __half g_Ah1[(size_t)BATCH * HID];
__device__ __half g_Al1[(size_t)BATCH * HID];
__device__ __half g_W16[(size_t)NLAYERS * FOURH * HID];   // gate-permuted, transposed

// ---------------------------------------------------------------------------
// PTX helpers (arch-agnostic: sm_80+)
// ---------------------------------------------------------------------------
__device__ __forceinline__ uint32_t smem_u32(const void* p) {
    uint32_t a;
    asm("{ .reg .u64 t; cvta.to.shared.u64 t, %1; cvt.u32.u64 %0, t; }" : "=r"(a) : "l"(p));
    return a;
}
__device__ __forceinline__ void cp_async16(uint32_t sdst, const void* gsrc) {
    asm volatile("cp.async.cg.shared.global [%0], [%1], 16;" :: "r"(sdst), "l"(gsrc));
}
__device__ __forceinline__ void cp_commit() { asm volatile("cp.async.commit_group;"); }
template <int N>
__device__ __forceinline__ void cp_wait() { asm volatile("cp.async.wait_group %0;" :: "n"(N)); }

__device__ __forceinline__ void ldm_x4(uint32_t* r, uint32_t addr) {
    asm volatile("ldmatrix.sync.aligned.m8n8.x4.shared.b16 {%0,%1,%2,%3}, [%4];"
                 : "=r"(r[0]), "=r"(r[1]), "=r"(r[2]), "=r"(r[3]) : "r"(addr));
}
__device__ __forceinline__ void mma16816(float* c, const uint32_t* a, const uint32_t* b) {
    asm volatile(
        "mma.sync.aligned.m16n8k16.row.col.f32.f16.f16.f32 "
        "{%0,%1,%2,%3}, {%4,%5,%6,%7}, {%8,%9}, {%0,%1,%2,%3};"
        : "+f"(c[0]), "+f"(c[1]), "+f"(c[2]), "+f"(c[3])
        : "r"(a[0]), "r"(a[1]), "r"(a[2]), "r"(a[3]), "r"(b[0]), "r"(b[1]));
}

// ---------------------------------------------------------------------------
// GEMM + fused LSTM gate epilogue + fused next-layer fp16 split.
// C = (Ah+Al) @ W16^T, 2 HMMA products. CTA tile 128x128, 8 warps (4Mx2N),
// warp tile 32x64. K chunks of 64 fp16, XOR-swizzled 128B rows (no padding),
// double-buffered; 96 KB/CTA -> 2 CTAs/SM with only 16 chunk barriers.
// Swizzle: 16B-chunk index c -> c ^ (row & 7). ldmatrix column reads hit 8
// distinct banks; cp.async row writes stay conflict-free.
// ---------------------------------------------------------------------------
#define KC        64
#define NCHUNKS   (HID / KC)               // 16
#define ROWB      128
#define REG_B     (128 * ROWB)             // 16384 B
#define STAGE_B   (3 * REG_B)              // 49152 B
#define GEMM_SMEM (2 * STAGE_B)            // 98304 B -> 2 CTAs/SM

__device__ __forceinline__ void load_region(const __half* g, int row0, int k0,
                                            uint32_t sdst, int tid) {
    const int row  = tid >> 1;
    const int half = tid & 1;
    const __half* src = g + (size_t)(row0 + row) * HID + k0 + half * 32;
    const uint32_t rbase = sdst + (uint32_t)row * ROWB;
    const int rm = row & 7;
    #pragma unroll
    for (int q = 0; q < 4; q++) {
        const int chunk = half * 4 + q;
        cp_async16(rbase + (uint32_t)((chunk ^ rm) << 4), src + q * 8);
    }
}

__global__ __launch_bounds__(256, 2) void gemm_lstm_fused(
    const __half* __restrict__ Ah, const __half* __restrict__ Al,
    const __half* __restrict__ Wh,
    const float* __restrict__ bias,       // [4H] original layout
    const float* __restrict__ rowx,       // [B] or nullptr (layer-0 x)
    const float* __restrict__ colw,       // [4H] or nullptr (layer-0 Wx0)
    const float* __restrict__ c_prev,     // [B,H]
    float* __restrict__ c_out,            // [B,H]
    float* __restrict__ h_out,            // [B,H]
    __half* __restrict__ nAh,             // next-layer A hi split (ping-pong)
    __half* __restrict__ nAl)
{
    extern __shared__ char smem[];
    const uint32_t sb = smem_u32(smem);

    const int tid    = threadIdx.x;
    const int wid    = tid >> 5;
    const int lane   = tid & 31;
    const int warp_m = wid & 3;
    const int warp_n = wid >> 2;
    const int bm = blockIdx.y * 128;
    const int bn = blockIdx.x * 128;

    // ldmatrix lane addressing (swizzled):
    // A: rows lane&15 (+16*mt), col-half (lane>>4); row&7 == lane&7.
    // B: rows ((lane>>4)<<3)|(lane&7) (+16*np), col-half (lane>>3)&1.
    const uint32_t swz   = (uint32_t)(lane & 7) << 4;     // same for A and B rows
    const int      arow  = lane & 15;
    const uint32_t acol  = (uint32_t)(lane >> 4) * 16;
    const int      brow  = ((lane >> 4) << 3) | (lane & 7);
    const uint32_t bcol  = (uint32_t)((lane >> 3) & 1) * 16;

    const uint32_t aRowOff = (uint32_t)(warp_m * 32 + arow) * ROWB;
    const uint32_t bRowOff = (uint32_t)(warp_n * 64 + brow) * ROWB;

    float acc[2][8][4];
    #pragma unroll
    for (int mt = 0; mt < 2; mt++)
        #pragma unroll
        for (int nt = 0; nt < 8; nt++)
            #pragma unroll
            for (int q = 0; q < 4; q++) acc[mt][nt][q] = 0.f;

    load_region(Ah, bm, 0, sb + 0 * REG_B, tid);
    load_region(Al, bm, 0, sb + 1 * REG_B, tid);
    load_region(Wh, bn, 0, sb + 2 * REG_B, tid);
    cp_commit();

    for (int c = 0; c < NCHUNKS; ++c) {
        if (c + 1 < NCHUNKS) {
            const uint32_t sbuf = sb + ((c + 1) & 1) * STAGE_B;
            const int k0 = (c + 1) * KC;
            load_region(Ah, bm, k0, sbuf + 0 * REG_B, tid);
            load_region(Al, bm, k0, sbuf + 1 * REG_B, tid);
            load_region(Wh, bn, k0, sbuf + 2 * REG_B, tid);
            cp_commit();
            cp_wait<1>();
        } else {
            cp_wait<0>();
        }
        __syncthreads();

        const uint32_t base  = sb + (c & 1) * STAGE_B;
        const uint32_t aBase = base + aRowOff;              // + region*REG_B
        const uint32_t bBase = base + 2 * REG_B + bRowOff;

        #pragma unroll
        for (int ks = 0; ks < 4; ks++) {
            const uint32_t ko = (uint32_t)ks * 32;          // 16 fp16 = 32 B
            const uint32_t aOff = (acol + ko) ^ swz;
            const uint32_t bOff = (bcol + ko) ^ swz;

            uint32_t ah[2][4], al[2][4], bh[4][4];
            #pragma unroll
            for (int np = 0; np < 4; np++)
                ldm_x4(bh[np], bBase + (uint32_t)np * 16 * ROWB + bOff);
            #pragma unroll
            for (int mt = 0; mt < 2; mt++)
                ldm_x4(ah[mt], aBase + 0 * REG_B + (uint32_t)mt * 16 * ROWB + aOff);

            #pragma unroll
            for (int mt = 0; mt < 2; mt++)
                #pragma unroll
                for (int nt = 0; nt < 8; nt++)
                    mma16816(acc[mt][nt], ah[mt], &bh[nt >> 1][(nt & 1) * 2]);

            #pragma unroll
            for (int mt = 0; mt < 2; mt++)
                ldm_x4(al[mt], aBase + 1 * REG_B + (uint32_t)mt * 16 * ROWB + aOff);
            #pragma unroll
            for (int mt = 0; mt < 2; mt++)
                #pragma unroll
                for (int nt = 0; nt < 8; nt++)
                    mma16816(acc[mt][nt], al[mt], &bh[nt >> 1][(nt & 1) * 2]);
        }
        __syncthreads();
    }

    // ---- fused LSTM gate epilogue ----
    const int quad = lane >> 2;
    const int glo  = lane & 1;
    const int joff = (lane >> 1) & 1;

    #pragma unroll
    for (int mt = 0; mt < 2; mt++) {
        const int rbase = bm + warp_m * 32 + mt * 16 + quad;
        #pragma unroll
        for (int nt = 0; nt < 8; nt++) {
            float v0 = acc[mt][nt][0], v1 = acc[mt][nt][1];
            float v2 = acc[mt][nt][2], v3 = acc[mt][nt][3];
            float r0 = __shfl_xor_sync(0xffffffffu, v0, 1);
            float r1 = __shfl_xor_sync(0xffffffffu, v1, 1);
            float r2 = __shfl_xor_sync(0xffffffffu, v2, 1);
            float r3 = __shfl_xor_sync(0xffffffffu, v3, 1);

            const int j = ((bn + warp_n * 64 + nt * 8) >> 2) + joff;
            int   m;
            float zi, zf, zg, zo;
            if (glo == 0) { m = rbase;     zi = v0; zf = v1; zg = r0; zo = r1; }
            else          { m = rbase + 8; zi = r2; zf = r3; zg = v2; zo = v3; }

            zi += bias[0 * HID + j];
            zf += bias[1 * HID + j];
            zg += bias[2 * HID + j];
            zo += bias[3 * HID + j];
            if (colw) {
                const float xv = rowx[m];
                zi = fmaf(xv, colw[0 * HID + j], zi);
                zf = fmaf(xv, colw[1 * HID + j], zf);
                zg = fmaf(xv, colw[2 * HID + j], zg);
                zo = fmaf(xv, colw[3 * HID + j], zo);
            }
            const float ig = 1.f / (1.f + expf(-zi));
            const float fg = 1.f / (1.f + expf(-zf));
            const float gg = tanhf(zg);
            const float og = 1.f / (1.f + expf(-zo));
            const size_t idx = (size_t)m * HID + j;
            const float cc = fmaf(fg, c_prev[idx], ig * gg);
            const float hh = og * tanhf(cc);
            c_out[idx] = cc;
            h_out[idx] = hh;
            const __half h_hi = __float2half_rn(hh);
            nAh[idx] = h_hi;
            nAl[idx] = __float2half_rn(hh - __half2float(h_hi));
        }
    }
}

// ---------------------------------------------------------------------------
// Weight prep (ALL layers, one launch): transpose, gate-permute, sum, fp16.
// ---------------------------------------------------------------------------
__global__ void wprep(const float* __restrict__ Wh0,
                      const float* __restrict__ Wx, const float* __restrict__ Whh,
                      __half* __restrict__ out)
{
    __shared__ float s[32][33];
    const int l  = blockIdx.z;
    const int k0 = blockIdx.x * 32, n0 = blockIdx.y * 32;
    const int tx = threadIdx.x, ty = threadIdx.y;
    const int n = n0 + tx;
    const int col = (n & 3) * HID + (n >> 2);
    float v;
    if (l == 0) {
        v = Wh0[(size_t)(k0 + ty) * FOURH + col];
    } else {
        const size_t off = (size_t)(l - 1) * HID * FOURH + (size_t)(k0 + ty) * FOURH + col;
        v = Wx[off] + Whh[off];
    }
    s[ty][tx] = v;
    __syncthreads();
    out[(size_t)l * FOURH * HID + (size_t)(n0 + ty) * HID + k0 + tx] =
        __float2half_rn(s[tx][ty]);
}

// ---------------------------------------------------------------------------
// h0 fp32 -> fp16 hi/lo split (vectorized x4)
// ---------------------------------------------------------------------------
__global__ void conv_a(const float* __restrict__ x,
                       __half* __restrict__ hi, __half* __restrict__ lo)
{
    const size_t i = (size_t)blockIdx.x * blockDim.x + threadIdx.x;
    float4 v = ((const float4*)x)[i];
    float vs[4] = {v.x, v.y, v.z, v.w};
    uint32_t ph[2], pl[2];
    #pragma unroll
    for (int p = 0; p < 2; p++) {
        uint32_t hw[2], lw[2];
        #pragma unroll
        for (int q = 0; q < 2; q++) {
            const float x0 = vs[2 * p + q];
            const __half hh = __float2half_rn(x0);
            hw[q] = (uint32_t)__half_as_ushort(hh);
            lw[q] = (uint32_t)__half_as_ushort(__float2half_rn(x0 - __half2float(hh)));
        }
        ph[p] = hw[0] | (hw[1] << 16);
        pl[p] = lw[0] | (lw[1] << 16);
    }
    ((uint2*)hi)[i] = make_uint2(ph[0], ph[1]);
    ((uint2*)lo)[i] = make_uint2(pl[0], pl[1]);
}

// ---------------------------------------------------------------------------
// Head: pred[b] = dot(h[b,:], Wd) + bd
// ---------------------------------------------------------------------------
__global__ void head_kernel(const float* __restrict__ h, const float* __restrict__ Wd,
                            const float* __restrict__ bd, float* __restrict__ pred, int B)
{
    const int row  = blockIdx.x * (blockDim.x >> 5) + (threadIdx.x >> 5);
    const int lane = threadIdx.x & 31;
    if (row >= B) return;
    const float* hr = h + (size_t)row * HID;
    float s = 0.f;
    #pragma unroll 8
    for (int k = lane; k < HID; k += 32) s = fmaf(hr[k], Wd[k], s);
    #pragma unroll
    for (int off = 16; off; off >>= 1) s += __shfl_down_sync(0xffffffffu, s, off);
    if (lane == 0) pred[row] = s + bd[0];
}

// ---------------------------------------------------------------------------
extern "C" void kernel_launch(void* const* d_in, const int* in_sizes, int n_in,
                              void* d_out, int out_size)
{
    const float* x_todec = (const float*)d_in[0];
    const float* c0      = (const float*)d_in[1];
    const float* h0      = (const float*)d_in[2];
    const float* Wx0     = (const float*)d_in[3];
    const float* Wh0     = (const float*)d_in[4];
    const float* b0      = (const float*)d_in[5];
    const float* Wx      = (const float*)d_in[6];
    const float* Wh      = (const float*)d_in[7];
    const float* bl      = (const float*)d_in[8];
    const float* Wd      = (const float*)d_in[9];
    const float* bd      = (const float*)d_in[10];

    float* out  = (float*)d_out;
    float* cbuf = out;
    float* hbuf = out + (size_t)BATCH * HID;
    float* pred = out + 2 * (size_t)BATCH * HID;

    __half *A0h, *A0l, *A1h, *A1l, *W16;
    cudaGetSymbolAddress((void**)&A0h, g_Ah0);
    cudaGetSymbolAddress((void**)&A0l, g_Al0);
    cudaGetSymbolAddress((void**)&A1h, g_Ah1);
    cudaGetSymbolAddress((void**)&A1l, g_Al1);
    cudaGetSymbolAddress((void**)&W16, g_W16);

    static bool attr_set = false;
    if (!attr_set) {
        cudaFuncSetAttribute(gemm_lstm_fused,
                             cudaFuncAttributeMaxDynamicSharedMemorySize, GEMM_SMEM);
        attr_set = true;
    }

    const dim3 ggrid(FOURH / 128, BATCH / 128);   // (32,64)

    wprep<<<dim3(HID / 32, FOURH / 32, NLAYERS), dim3(32, 32)>>>(Wh0, Wx, Wh, W16);
    conv_a<<<(BATCH * HID / 4) / 256, 256>>>(h0, A0h, A0l);

    __half* curh = A0h; __half* curl = A0l;
    __half* nxth = A1h; __half* nxtl = A1l;

    // layer 0: z = h0 @ Wh0^T (+ x*Wx0 + b0 in epilogue)
    gemm_lstm_fused<<<ggrid, 256, GEMM_SMEM>>>(curh, curl, W16,
                                               b0, x_todec, Wx0,
                                               c0, cbuf, hbuf, nxth, nxtl);
    // layers 1..3: z = h @ (Wx+Wh)^T + b
    for (int l = 1; l < NLAYERS; l++) {
        __half* th = curh; __half* tl = curl;
        curh = nxth; curl = nxtl;
        nxth = th;   nxtl = tl;
        gemm_lstm_fused<<<ggrid, 256, GEMM_SMEM>>>(curh, curl,
                                                   W16 + (size_t)l * FOURH * HID,
                                                   bl + (size_t)(l - 1) * FOURH,
                                                   nullptr, nullptr,
                                                   cbuf, cbuf, hbuf, nxth, nxtl);
    }

    head_kernel<<<BATCH / 8, 256>>>(hbuf, Wd, bd, pred, BATCH);
}

// round 9
// speedup vs baseline: 4.9771x; 1.5179x over previous
#include <cuda_runtime.h>
#include <cuda_fp16.h>
#include <cstdint>
#include <math.h>

#define BATCH 8192
#define HID   1024
#define FOURH 4096
#define NLAYERS 4

// ---------------------------------------------------------------------------
// Scratch (allocation-free). Ping-pong activation buffers (cross-CTA safety).
// ---------------------------------------------------------------------------
__device__ __half g_A0[(size_t)BATCH * HID];
__device__ __half g_A1[(size_t)BATCH * HID];
__device__ __half g_W16[(size_t)NLAYERS * FOURH * HID];   // gate-permuted, transposed

// ---------------------------------------------------------------------------
// PTX helpers (arch-agnostic: sm_80+)
// ---------------------------------------------------------------------------
__device__ __forceinline__ uint32_t smem_u32(const void* p) {
    uint32_t a;
    asm("{ .reg .u64 t; cvta.to.shared.u64 t, %1; cvt.u32.u64 %0, t; }" : "=r"(a) : "l"(p));
    return a;
}
__device__ __forceinline__ void cp_async16(uint32_t sdst, const void* gsrc) {
    asm volatile("cp.async.cg.shared.global [%0], [%1], 16;" :: "r"(sdst), "l"(gsrc));
}
__device__ __forceinline__ void cp_commit() { asm volatile("cp.async.commit_group;"); }
template <int N>
__device__ __forceinline__ void cp_wait() { asm volatile("cp.async.wait_group %0;" :: "n"(N)); }

__device__ __forceinline__ void ldm_x4(uint32_t* r, uint32_t addr) {
    asm volatile("ldmatrix.sync.aligned.m8n8.x4.shared.b16 {%0,%1,%2,%3}, [%4];"
                 : "=r"(r[0]), "=r"(r[1]), "=r"(r[2]), "=r"(r[3]) : "r"(addr));
}
__device__ __forceinline__ void mma16816(float* c, const uint32_t* a, const uint32_t* b) {
    asm volatile(
        "mma.sync.aligned.m16n8k16.row.col.f32.f16.f16.f32 "
        "{%0,%1,%2,%3}, {%4,%5,%6,%7}, {%8,%9}, {%0,%1,%2,%3};"
        : "+f"(c[0]), "+f"(c[1]), "+f"(c[2]), "+f"(c[3])
        : "r"(a[0]), "r"(a[1]), "r"(a[2]), "r"(a[3]), "r"(b[0]), "r"(b[1]));
}

// ---------------------------------------------------------------------------
// GEMM + fused LSTM gate epilogue + fused next-layer fp16 convert.
// C = A @ W16^T, SINGLE fp16 product. CTA tile 128x128, 8 warps (4Mx2N),
// warp tile 32x64. K chunks of 64 fp16, XOR-swizzled 128B rows,
// double-buffered; 64 KB/CTA -> 2 CTAs/SM.
// Swizzle: 16B-chunk index c -> c ^ (row & 7).
// ---------------------------------------------------------------------------
#define KC        64
#define NCHUNKS   (HID / KC)               // 16
#define ROWB      128
#define REG_B     (128 * ROWB)             // 16384 B
#define STAGE_B   (2 * REG_B)              // 32768 B (A, W)
#define GEMM_SMEM (2 * STAGE_B)            // 65536 B -> 2 CTAs/SM

__device__ __forceinline__ void load_region(const __half* g, int row0, int k0,
                                            uint32_t sdst, int tid) {
    const int row  = tid >> 1;
    const int half = tid & 1;
    const __half* src = g + (size_t)(row0 + row) * HID + k0 + half * 32;
    const uint32_t rbase = sdst + (uint32_t)row * ROWB;
    const int rm = row & 7;
    #pragma unroll
    for (int q = 0; q < 4; q++) {
        const int chunk = half * 4 + q;
        cp_async16(rbase + (uint32_t)((chunk ^ rm) << 4), src + q * 8);
    }
}

__global__ __launch_bounds__(256, 2) void gemm_lstm_fused(
    const __half* __restrict__ A,
    const __half* __restrict__ Wh,
    const float* __restrict__ bias,       // [4H] original layout
    const float* __restrict__ rowx,       // [B] or nullptr (layer-0 x)
    const float* __restrict__ colw,       // [4H] or nullptr (layer-0 Wx0)
    const float* __restrict__ c_prev,     // [B,H]
    float* __restrict__ c_out,            // [B,H]
    float* __restrict__ h_out,            // [B,H]
    __half* __restrict__ nA)              // next-layer A (ping-pong buf)
{
    extern __shared__ char smem[];
    const uint32_t sb = smem_u32(smem);

    const int tid    = threadIdx.x;
    const int wid    = tid >> 5;
    const int lane   = tid & 31;
    const int warp_m = wid & 3;
    const int warp_n = wid >> 2;
    const int bm = blockIdx.y * 128;
    const int bn = blockIdx.x * 128;

    const uint32_t swz   = (uint32_t)(lane & 7) << 4;
    const int      arow  = lane & 15;
    const uint32_t acol  = (uint32_t)(lane >> 4) * 16;
    const int      brow  = ((lane >> 4) << 3) | (lane & 7);
    const uint32_t bcol  = (uint32_t)((lane >> 3) & 1) * 16;

    const uint32_t aRowOff = (uint32_t)(warp_m * 32 + arow) * ROWB;
    const uint32_t bRowOff = (uint32_t)(warp_n * 64 + brow) * ROWB;

    float acc[2][8][4];
    #pragma unroll
    for (int mt = 0; mt < 2; mt++)
        #pragma unroll
        for (int nt = 0; nt < 8; nt++)
            #pragma unroll
            for (int q = 0; q < 4; q++) acc[mt][nt][q] = 0.f;

    load_region(A,  bm, 0, sb + 0 * REG_B, tid);
    load_region(Wh, bn, 0, sb + 1 * REG_B, tid);
    cp_commit();

    for (int c = 0; c < NCHUNKS; ++c) {
        if (c + 1 < NCHUNKS) {
            const uint32_t sbuf = sb + ((c + 1) & 1) * STAGE_B;
            const int k0 = (c + 1) * KC;
            load_region(A,  bm, k0, sbuf + 0 * REG_B, tid);
            load_region(Wh, bn, k0, sbuf + 1 * REG_B, tid);
            cp_commit();
            cp_wait<1>();
        } else {
            cp_wait<0>();
        }
        __syncthreads();

        const uint32_t base  = sb + (c & 1) * STAGE_B;
        const uint32_t aBase = base + aRowOff;
        const uint32_t bBase = base + REG_B + bRowOff;

        #pragma unroll
        for (int ks = 0; ks < 4; ks++) {
            const uint32_t ko = (uint32_t)ks * 32;          // 16 fp16 = 32 B
            const uint32_t aOff = (acol + ko) ^ swz;
            const uint32_t bOff = (bcol + ko) ^ swz;

            uint32_t ah[2][4], bh[4][4];
            #pragma unroll
            for (int np = 0; np < 4; np++)
                ldm_x4(bh[np], bBase + (uint32_t)np * 16 * ROWB + bOff);
            #pragma unroll
            for (int mt = 0; mt < 2; mt++)
                ldm_x4(ah[mt], aBase + (uint32_t)mt * 16 * ROWB + aOff);

            #pragma unroll
            for (int mt = 0; mt < 2; mt++)
                #pragma unroll
                for (int nt = 0; nt < 8; nt++)
                    mma16816(acc[mt][nt], ah[mt], &bh[nt >> 1][(nt & 1) * 2]);
        }
        __syncthreads();
    }

    // ---- fused LSTM gate epilogue ----
    const int quad = lane >> 2;
    const int glo  = lane & 1;
    const int joff = (lane >> 1) & 1;

    #pragma unroll
    for (int mt = 0; mt < 2; mt++) {
        const int rbase = bm + warp_m * 32 + mt * 16 + quad;
        #pragma unroll
        for (int nt = 0; nt < 8; nt++) {
            float v0 = acc[mt][nt][0], v1 = acc[mt][nt][1];
            float v2 = acc[mt][nt][2], v3 = acc[mt][nt][3];
            float r0 = __shfl_xor_sync(0xffffffffu, v0, 1);
            float r1 = __shfl_xor_sync(0xffffffffu, v1, 1);
            float r2 = __shfl_xor_sync(0xffffffffu, v2, 1);
            float r3 = __shfl_xor_sync(0xffffffffu, v3, 1);

            const int j = ((bn + warp_n * 64 + nt * 8) >> 2) + joff;
            int   m;
            float zi, zf, zg, zo;
            if (glo == 0) { m = rbase;     zi = v0; zf = v1; zg = r0; zo = r1; }
            else          { m = rbase + 8; zi = r2; zf = r3; zg = v2; zo = v3; }

            zi += bias[0 * HID + j];
            zf += bias[1 * HID + j];
            zg += bias[2 * HID + j];
            zo += bias[3 * HID + j];
            if (colw) {
                const float xv = rowx[m];
                zi = fmaf(xv, colw[0 * HID + j], zi);
                zf = fmaf(xv, colw[1 * HID + j], zf);
                zg = fmaf(xv, colw[2 * HID + j], zg);
                zo = fmaf(xv, colw[3 * HID + j], zo);
            }
            const float ig = 1.f / (1.f + expf(-zi));
            const float fg = 1.f / (1.f + expf(-zf));
            const float gg = tanhf(zg);
            const float og = 1.f / (1.f + expf(-zo));
            const size_t idx = (size_t)m * HID + j;
            const float cc = fmaf(fg, c_prev[idx], ig * gg);
            const float hh = og * tanhf(cc);
            c_out[idx] = cc;
            h_out[idx] = hh;
            nA[idx] = __float2half_rn(hh);
        }
    }
}

// ---------------------------------------------------------------------------
// Weight prep (ALL layers, one launch): transpose, gate-permute, sum, fp16.
// ---------------------------------------------------------------------------
__global__ void wprep(const float* __restrict__ Wh0,
                      const float* __restrict__ Wx, const float* __restrict__ Whh,
                      __half* __restrict__ out)
{
    __shared__ float s[32][33];
    const int l  = blockIdx.z;
    const int k0 = blockIdx.x * 32, n0 = blockIdx.y * 32;
    const int tx = threadIdx.x, ty = threadIdx.y;
    const int n = n0 + tx;
    const int col = (n & 3) * HID + (n >> 2);
    float v;
    if (l == 0) {
        v = Wh0[(size_t)(k0 + ty) * FOURH + col];
    } else {
        const size_t off = (size_t)(l - 1) * HID * FOURH + (size_t)(k0 + ty) * FOURH + col;
        v = Wx[off] + Whh[off];
    }
    s[ty][tx] = v;
    __syncthreads();
    out[(size_t)l * FOURH * HID + (size_t)(n0 + ty) * HID + k0 + tx] =
        __float2half_rn(s[tx][ty]);
}

// ---------------------------------------------------------------------------
// h0 fp32 -> fp16 (vectorized x4)
// ---------------------------------------------------------------------------
__global__ void conv_a(const float* __restrict__ x, __half* __restrict__ o)
{
    const size_t i = (size_t)blockIdx.x * blockDim.x + threadIdx.x;
    float4 v = ((const float4*)x)[i];
    uint32_t p0 = (uint32_t)__half_as_ushort(__float2half_rn(v.x))
                | ((uint32_t)__half_as_ushort(__float2half_rn(v.y)) << 16);
    uint32_t p1 = (uint32_t)__half_as_ushort(__float2half_rn(v.z))
                | ((uint32_t)__half_as_ushort(__float2half_rn(v.w)) << 16);
    ((uint2*)o)[i] = make_uint2(p0, p1);
}

// ---------------------------------------------------------------------------
// Head: pred[b] = dot(h[b,:], Wd) + bd
// ---------------------------------------------------------------------------
__global__ void head_kernel(const float* __restrict__ h, const float* __restrict__ Wd,
                            const float* __restrict__ bd, float* __restrict__ pred, int B)
{
    const int row  = blockIdx.x * (blockDim.x >> 5) + (threadIdx.x >> 5);
    const int lane = threadIdx.x & 31;
    if (row >= B) return;
    const float* hr = h + (size_t)row * HID;
    float s = 0.f;
    #pragma unroll 8
    for (int k = lane; k < HID; k += 32) s = fmaf(hr[k], Wd[k], s);
    #pragma unroll
    for (int off = 16; off; off >>= 1) s += __shfl_down_sync(0xffffffffu, s, off);
    if (lane == 0) pred[row] = s + bd[0];
}

// ---------------------------------------------------------------------------
extern "C" void kernel_launch(void* const* d_in, const int* in_sizes, int n_in,
                              void* d_out, int out_size)
{
    const float* x_todec = (const float*)d_in[0];
    const float* c0      = (const float*)d_in[1];
    const float* h0      = (const float*)d_in[2];
    const float* Wx0     = (const float*)d_in[3];
    const float* Wh0     = (const float*)d_in[4];
    const float* b0      = (const float*)d_in[5];
    const float* Wx      = (const float*)d_in[6];
    const float* Wh      = (const float*)d_in[7];
    const float* bl      = (const float*)d_in[8];
    const float* Wd      = (const float*)d_in[9];
    const float* bd      = (const float*)d_in[10];

    float* out  = (float*)d_out;
    float* cbuf = out;
    float* hbuf = out + (size_t)BATCH * HID;
    float* pred = out + 2 * (size_t)BATCH * HID;

    __half *A0, *A1, *W16;
    cudaGetSymbolAddress((void**)&A0, g_A0);
    cudaGetSymbolAddress((void**)&A1, g_A1);
    cudaGetSymbolAddress((void**)&W16, g_W16);

    static bool attr_set = false;
    if (!attr_set) {
        cudaFuncSetAttribute(gemm_lstm_fused,
                             cudaFuncAttributeMaxDynamicSharedMemorySize, GEMM_SMEM);
        attr_set = true;
    }

    const dim3 ggrid(FOURH / 128, BATCH / 128);   // (32,64)

    wprep<<<dim3(HID / 32, FOURH / 32, NLAYERS), dim3(32, 32)>>>(Wh0, Wx, Wh, W16);
    conv_a<<<(BATCH * HID / 4) / 256, 256>>>(h0, A0);

    __half* cur = A0;
    __half* nxt = A1;

    // layer 0: z = h0 @ Wh0^T (+ x*Wx0 + b0 in epilogue)
    gemm_lstm_fused<<<ggrid, 256, GEMM_SMEM>>>(cur, W16,
                                               b0, x_todec, Wx0,
                                               c0, cbuf, hbuf, nxt);
    // layers 1..3: z = h @ (Wx+Wh)^T + b
    for (int l = 1; l < NLAYERS; l++) {
        __half* t = cur; cur = nxt; nxt = t;
        gemm_lstm_fused<<<ggrid, 256, GEMM_SMEM>>>(cur,
                                                   W16 + (size_t)l * FOURH * HID,
                                                   bl + (size_t)(l - 1) * FOURH,
                                                   nullptr, nullptr,
                                                   cbuf, cbuf, hbuf, nxt);
    }

    head_kernel<<<BATCH / 8, 256>>>(hbuf, Wd, bd, pred, BATCH);
}

// round 10
// speedup vs baseline: 5.7642x; 1.1581x over previous
#include <cuda_runtime.h>
#include <cuda_fp16.h>
#include <cstdint>
#include <math.h>

#define BATCH 8192
#define HID   1024
#define FOURH 4096
#define NLAYERS 4

// ---------------------------------------------------------------------------
// Scratch (allocation-free). Ping-pong activation buffers (cross-CTA safety).
// ---------------------------------------------------------------------------
__device__ __half g_A0[(size_t)BATCH * HID];
__device__ __half g_A1[(size_t)BATCH * HID];
__device__ __half g_W16[(size_t)NLAYERS * FOURH * HID];   // gate-permuted, transposed

// ---------------------------------------------------------------------------
// PTX helpers (arch-agnostic: sm_80+)
// ---------------------------------------------------------------------------
__device__ __forceinline__ uint32_t smem_u32(const void* p) {
    uint32_t a;
    asm("{ .reg .u64 t; cvta.to.shared.u64 t, %1; cvt.u32.u64 %0, t; }" : "=r"(a) : "l"(p));
    return a;
}
__device__ __forceinline__ void cp_async16(uint32_t sdst, const void* gsrc) {
    asm volatile("cp.async.cg.shared.global [%0], [%1], 16;" :: "r"(sdst), "l"(gsrc));
}
__device__ __forceinline__ void cp_commit() { asm volatile("cp.async.commit_group;"); }
template <int N>
__device__ __forceinline__ void cp_wait() { asm volatile("cp.async.wait_group %0;" :: "n"(N)); }

__device__ __forceinline__ void ldm_x4(uint32_t* r, uint32_t addr) {
    asm volatile("ldmatrix.sync.aligned.m8n8.x4.shared.b16 {%0,%1,%2,%3}, [%4];"
                 : "=r"(r[0]), "=r"(r[1]), "=r"(r[2]), "=r"(r[3]) : "r"(addr));
}
__device__ __forceinline__ void mma16816(float* c, const uint32_t* a, const uint32_t* b) {
    asm volatile(
        "mma.sync.aligned.m16n8k16.row.col.f32.f16.f16.f32 "
        "{%0,%1,%2,%3}, {%4,%5,%6,%7}, {%8,%9}, {%0,%1,%2,%3};"
        : "+f"(c[0]), "+f"(c[1]), "+f"(c[2]), "+f"(c[3])
        : "r"(a[0]), "r"(a[1]), "r"(a[2]), "r"(a[3]), "r"(b[0]), "r"(b[1]));
}
__device__ __forceinline__ void sts64(uint32_t addr, float x, float y) {
    asm volatile("st.shared.v2.f32 [%0], {%1, %2};" :: "r"(addr), "f"(x), "f"(y));
}
__device__ __forceinline__ float4 lds128(uint32_t addr) {
    float4 v;
    asm volatile("ld.shared.v4.f32 {%0,%1,%2,%3}, [%4];"
                 : "=f"(v.x), "=f"(v.y), "=f"(v.z), "=f"(v.w) : "r"(addr));
    return v;
}

// ---------------------------------------------------------------------------
// GEMM + fused LSTM gate epilogue + fused next-layer fp16 convert.
// C = A @ W16^T, single fp16 product. CTA tile 128x128, 8 warps (4Mx2N),
// warp tile 32x64. K chunks of 64 fp16, XOR-swizzled 128B rows,
// double-buffered. Warps start ks at (ks+wid)&3 to de-phase LDSM/MMA bursts.
// Epilogue stages z in smem (528B row stride) for coalesced gmem I/O.
// ---------------------------------------------------------------------------
#define KC        64
#define NCHUNKS   (HID / KC)               // 16
#define ROWB      128
#define REG_B     (128 * ROWB)             // 16384 B
#define STAGE_B   (2 * REG_B)              // 32768 B (A, W)
#define ZROWB     528                      // epilogue fp32 row stride
#define GEMM_SMEM (128 * ZROWB)            // 67584 B (mainloop uses 65536)

__device__ __forceinline__ void load_region(const __half* g, int row0, int k0,
                                            uint32_t sdst, int tid) {
    const int row  = tid >> 1;
    const int half = tid & 1;
    const __half* src = g + (size_t)(row0 + row) * HID + k0 + half * 32;
    const uint32_t rbase = sdst + (uint32_t)row * ROWB;
    const int rm = row & 7;
    #pragma unroll
    for (int q = 0; q < 4; q++) {
        const int chunk = half * 4 + q;
        cp_async16(rbase + (uint32_t)((chunk ^ rm) << 4), src + q * 8);
    }
}

__global__ __launch_bounds__(256, 2) void gemm_lstm_fused(
    const __half* __restrict__ A,
    const __half* __restrict__ Wh,
    const float* __restrict__ bias,       // [4H] original layout
    const float* __restrict__ rowx,       // [B] or nullptr (layer-0 x)
    const float* __restrict__ colw,       // [4H] or nullptr (layer-0 Wx0)
    const float* __restrict__ c_prev,     // [B,H]
    float* __restrict__ c_out,            // [B,H]
    float* __restrict__ h_out,            // [B,H]
    __half* __restrict__ nA)              // next-layer A (ping-pong buf)
{
    extern __shared__ char smem[];
    const uint32_t sb = smem_u32(smem);

    const int tid    = threadIdx.x;
    const int wid    = tid >> 5;
    const int lane   = tid & 31;
    const int warp_m = wid & 3;
    const int warp_n = wid >> 2;
    const int bm = blockIdx.y * 128;
    const int bn = blockIdx.x * 128;

    const uint32_t swz   = (uint32_t)(lane & 7) << 4;
    const int      arow  = lane & 15;
    const uint32_t acol  = (uint32_t)(lane >> 4) * 16;
    const int      brow  = ((lane >> 4) << 3) | (lane & 7);
    const uint32_t bcol  = (uint32_t)((lane >> 3) & 1) * 16;

    const uint32_t aRowOff = (uint32_t)(warp_m * 32 + arow) * ROWB;
    const uint32_t bRowOff = (uint32_t)(warp_n * 64 + brow) * ROWB;

    float acc[2][8][4];
    #pragma unroll
    for (int mt = 0; mt < 2; mt++)
        #pragma unroll
        for (int nt = 0; nt < 8; nt++)
            #pragma unroll
            for (int q = 0; q < 4; q++) acc[mt][nt][q] = 0.f;

    load_region(A,  bm, 0, sb + 0 * REG_B, tid);
    load_region(Wh, bn, 0, sb + 1 * REG_B, tid);
    cp_commit();

    for (int c = 0; c < NCHUNKS; ++c) {
        if (c + 1 < NCHUNKS) {
            const uint32_t sbuf = sb + ((c + 1) & 1) * STAGE_B;
            const int k0 = (c + 1) * KC;
            load_region(A,  bm, k0, sbuf + 0 * REG_B, tid);
            load_region(Wh, bn, k0, sbuf + 1 * REG_B, tid);
            cp_commit();
            cp_wait<1>();
        } else {
            cp_wait<0>();
        }
        __syncthreads();

        const uint32_t base  = sb + (c & 1) * STAGE_B;
        const uint32_t aBase = base + aRowOff;
        const uint32_t bBase = base + REG_B + bRowOff;

        #pragma unroll
        for (int kk = 0; kk < 4; kk++) {
            const int ks = (kk + wid) & 3;                  // de-phase warps
            const uint32_t ko = (uint32_t)ks * 32;          // 16 fp16 = 32 B
            const uint32_t aOff = (acol + ko) ^ swz;
            const uint32_t bOff = (bcol + ko) ^ swz;

            uint32_t ah[2][4], bh[4][4];
            #pragma unroll
            for (int np = 0; np < 4; np++)
                ldm_x4(bh[np], bBase + (uint32_t)np * 16 * ROWB + bOff);
            #pragma unroll
            for (int mt = 0; mt < 2; mt++)
                ldm_x4(ah[mt], aBase + (uint32_t)mt * 16 * ROWB + aOff);

            #pragma unroll
            for (int mt = 0; mt < 2; mt++)
                #pragma unroll
                for (int nt = 0; nt < 8; nt++)
                    mma16816(acc[mt][nt], ah[mt], &bh[nt >> 1][(nt & 1) * 2]);
        }
        __syncthreads();
    }

    // ---- epilogue phase 1: stage z tile to smem (row stride 528B) ----
    {
        const int quad = lane >> 2;
        const uint32_t ncol = (uint32_t)(warp_n * 64 + 2 * (lane & 3)) * 4;
        #pragma unroll
        for (int mt = 0; mt < 2; mt++) {
            const uint32_t m0 = (uint32_t)(warp_m * 32 + mt * 16 + quad);
            #pragma unroll
            for (int nt = 0; nt < 8; nt++) {
                const uint32_t a0 = sb + m0 * ZROWB + ncol + (uint32_t)nt * 32;
                sts64(a0,             acc[mt][nt][0], acc[mt][nt][1]);
                sts64(a0 + 8 * ZROWB, acc[mt][nt][2], acc[mt][nt][3]);
            }
        }
    }
    __syncthreads();

    // ---- epilogue phase 2: gates + cell update, fully coalesced gmem ----
    {
        const int jb   = tid & 7;            // j-block of 4
        const int mrow = tid >> 3;           // 0..31
        const int jcol = (bn >> 2) + jb * 4; // hidden index base (4 consecutive)

        const float4 bi = *(const float4*)(bias + 0 * HID + jcol);
        const float4 bf = *(const float4*)(bias + 1 * HID + jcol);
        const float4 bg = *(const float4*)(bias + 2 * HID + jcol);
        const float4 bo = *(const float4*)(bias + 3 * HID + jcol);
        float4 wi, wf, wg, wo;
        if (colw) {
            wi = *(const float4*)(colw + 0 * HID + jcol);
            wf = *(const float4*)(colw + 1 * HID + jcol);
            wg = *(const float4*)(colw + 2 * HID + jcol);
            wo = *(const float4*)(colw + 3 * HID + jcol);
        }

        #pragma unroll
        for (int mi = 0; mi < 4; mi++) {
            const int m_local = mrow + 32 * mi;
            const int m = bm + m_local;
            const uint32_t zb = sb + (uint32_t)m_local * ZROWB + (uint32_t)jb * 64;
            float4 z0 = lds128(zb);        // j+0: (zi,zf,zg,zo)
            float4 z1 = lds128(zb + 16);   // j+1
            float4 z2 = lds128(zb + 32);   // j+2
            float4 z3 = lds128(zb + 48);   // j+3

            const size_t gidx = (size_t)m * HID + jcol;
            const float4 cp = *(const float4*)(c_prev + gidx);
            const float xv = colw ? rowx[m] : 0.f;

            float zi[4] = {z0.x + bi.x, z1.x + bi.y, z2.x + bi.z, z3.x + bi.w};
            float zf[4] = {z0.y + bf.x, z1.y + bf.y, z2.y + bf.z, z3.y + bf.w};
            float zg[4] = {z0.z + bg.x, z1.z + bg.y, z2.z + bg.z, z3.z + bg.w};
            float zo[4] = {z0.w + bo.x, z1.w + bo.y, z2.w + bo.z, z3.w + bo.w};
            if (colw) {
                zi[0] = fmaf(xv, wi.x, zi[0]); zi[1] = fmaf(xv, wi.y, zi[1]);
                zi[2] = fmaf(xv, wi.z, zi[2]); zi[3] = fmaf(xv, wi.w, zi[3]);
                zf[0] = fmaf(xv, wf.x, zf[0]); zf[1] = fmaf(xv, wf.y, zf[1]);
                zf[2] = fmaf(xv, wf.z, zf[2]); zf[3] = fmaf(xv, wf.w, zf[3]);
                zg[0] = fmaf(xv, wg.x, zg[0]); zg[1] = fmaf(xv, wg.y, zg[1]);
                zg[2] = fmaf(xv, wg.z, zg[2]); zg[3] = fmaf(xv, wg.w, zg[3]);
                zo[0] = fmaf(xv, wo.x, zo[0]); zo[1] = fmaf(xv, wo.y, zo[1]);
                zo[2] = fmaf(xv, wo.z, zo[2]); zo[3] = fmaf(xv, wo.w, zo[3]);
            }
            const float cpv[4] = {cp.x, cp.y, cp.z, cp.w};
            float4 co, ho;
            float* cop = &co.x;
            float* hop = &ho.x;
            __half hv[4];
            #pragma unroll
            for (int q = 0; q < 4; q++) {
                const float ig = 1.f / (1.f + expf(-zi[q]));
                const float fg = 1.f / (1.f + expf(-zf[q]));
                const float gg = tanhf(zg[q]);
                const float og = 1.f / (1.f + expf(-zo[q]));
                const float cc = fmaf(fg, cpv[q], ig * gg);
                const float hh = og * tanhf(cc);
                cop[q] = cc;
                hop[q] = hh;
                hv[q] = __float2half_rn(hh);
            }
            *(float4*)(c_out + gidx) = co;
            *(float4*)(h_out + gidx) = ho;
            *(uint2*)(nA + gidx) = make_uint2(
                (uint32_t)__half_as_ushort(hv[0]) | ((uint32_t)__half_as_ushort(hv[1]) << 16),
                (uint32_t)__half_as_ushort(hv[2]) | ((uint32_t)__half_as_ushort(hv[3]) << 16));
        }
    }
}

// ---------------------------------------------------------------------------
// Weight prep (ALL layers, one launch): transpose, gate-permute, sum, fp16.
// ---------------------------------------------------------------------------
__global__ void wprep(const float* __restrict__ Wh0,
                      const float* __restrict__ Wx, const float* __restrict__ Whh,
                      __half* __restrict__ out)
{
    __shared__ float s[32][33];
    const int l  = blockIdx.z;
    const int k0 = blockIdx.x * 32, n0 = blockIdx.y * 32;
    const int tx = threadIdx.x, ty = threadIdx.y;
    const int n = n0 + tx;
    const int col = (n & 3) * HID + (n >> 2);
    float v;
    if (l == 0) {
        v = Wh0[(size_t)(k0 + ty) * FOURH + col];
    } else {
        const size_t off = (size_t)(l - 1) * HID * FOURH + (size_t)(k0 + ty) * FOURH + col;
        v = Wx[off] + Whh[off];
    }
    s[ty][tx] = v;
    __syncthreads();
    out[(size_t)l * FOURH * HID + (size_t)(n0 + ty) * HID + k0 + tx] =
        __float2half_rn(s[tx][ty]);
}

// ---------------------------------------------------------------------------
// h0 fp32 -> fp16 (vectorized x4)
// ---------------------------------------------------------------------------
__global__ void conv_a(const float* __restrict__ x, __half* __restrict__ o)
{
    const size_t i = (size_t)blockIdx.x * blockDim.x + threadIdx.x;
    float4 v = ((const float4*)x)[i];
    uint32_t p0 = (uint32_t)__half_as_ushort(__float2half_rn(v.x))
                | ((uint32_t)__half_as_ushort(__float2half_rn(v.y)) << 16);
    uint32_t p1 = (uint32_t)__half_as_ushort(__float2half_rn(v.z))
                | ((uint32_t)__half_as_ushort(__float2half_rn(v.w)) << 16);
    ((uint2*)o)[i] = make_uint2(p0, p1);
}

// ---------------------------------------------------------------------------
// Head: pred[b] = dot(h[b,:], Wd) + bd
// ---------------------------------------------------------------------------
__global__ void head_kernel(const float* __restrict__ h, const float* __restrict__ Wd,
                            const float* __restrict__ bd, float* __restrict__ pred, int B)
{
    const int row  = blockIdx.x * (blockDim.x >> 5) + (threadIdx.x >> 5);
    const int lane = threadIdx.x & 31;
    if (row >= B) return;
    const float* hr = h + (size_t)row * HID;
    float s = 0.f;
    #pragma unroll 8
    for (int k = lane; k < HID; k += 32) s = fmaf(hr[k], Wd[k], s);
    #pragma unroll
    for (int off = 16; off; off >>= 1) s += __shfl_down_sync(0xffffffffu, s, off);
    if (lane == 0) pred[row] = s + bd[0];
}

// ---------------------------------------------------------------------------
extern "C" void kernel_launch(void* const* d_in, const int* in_sizes, int n_in,
                              void* d_out, int out_size)
{
    const float* x_todec = (const float*)d_in[0];
    const float* c0      = (const float*)d_in[1];
    const float* h0      = (const float*)d_in[2];
    const float* Wx0     = (const float*)d_in[3];
    const float* Wh0     = (const float*)d_in[4];
    const float* b0      = (const float*)d_in[5];
    const float* Wx      = (const float*)d_in[6];
    const float* Wh      = (const float*)d_in[7];
    const float* bl      = (const float*)d_in[8];
    const float* Wd      = (const float*)d_in[9];
    const float* bd      = (const float*)d_in[10];

    float* out  = (float*)d_out;
    float* cbuf = out;
    float* hbuf = out + (size_t)BATCH * HID;
    float* pred = out + 2 * (size_t)BATCH * HID;

    __half *A0, *A1, *W16;
    cudaGetSymbolAddress((void**)&A0, g_A0);
    cudaGetSymbolAddress((void**)&A1, g_A1);
    cudaGetSymbolAddress((void**)&W16, g_W16);

    static bool attr_set = false;
    if (!attr_set) {
        cudaFuncSetAttribute(gemm_lstm_fused,
                             cudaFuncAttributeMaxDynamicSharedMemorySize, GEMM_SMEM);
        attr_set = true;
    }

    const dim3 ggrid(FOURH / 128, BATCH / 128);   // (32,64)

    wprep<<<dim3(HID / 32, FOURH / 32, NLAYERS), dim3(32, 32)>>>(Wh0, Wx, Wh, W16);
    conv_a<<<(BATCH * HID / 4) / 256, 256>>>(h0, A0);

    __half* cur = A0;
    __half* nxt = A1;

    // layer 0: z = h0 @ Wh0^T (+ x*Wx0 + b0 in epilogue)
    gemm_lstm_fused<<<ggrid, 256, GEMM_SMEM>>>(cur, W16,
                                               b0, x_todec, Wx0,
                                               c0, cbuf, hbuf, nxt);
    // layers 1..3: z = h @ (Wx+Wh)^T + b
    for (int l = 1; l < NLAYERS; l++) {
        __half* t = cur; cur = nxt; nxt = t;
        gemm_lstm_fused<<<ggrid, 256, GEMM_SMEM>>>(cur,
                                                   W16 + (size_t)l * FOURH * HID,
                                                   bl + (size_t)(l - 1) * FOURH,
                                                   nullptr, nullptr,
                                                   cbuf, cbuf, hbuf, nxt);
    }

    head_kernel<<<BATCH / 8, 256>>>(hbuf, Wd, bd, pred, BATCH);
}